// round 1
// baseline (speedup 1.0000x reference)
#include <cuda_runtime.h>
#include <math.h>

// Problem dims (fixed per reference)
#define BATCH   1024
#define IN_DIM  1024
#define HID     4096
#define KX      (IN_DIM + HID)   // 5120
#define G4      (4 * HID)        // 16384
#define OUT_DIM 4096

// ---------------- scratch (no cudaMalloc allowed) ----------------
__device__ float g_x[BATCH * KX];          // [B, 5120] concat(i,h)
__device__ float g_gates[BATCH * G4];      // [B, 16384] pre-activation gates (no bias)
__device__ float g_ht[BATCH * HID];        // [B, 4096]
__device__ float g_logits[BATCH * OUT_DIM];// [B, 4096] pre-softmax (no bias)

// ---------------- concat(i, h) -> g_x ----------------
__global__ void concat_kernel(const float* __restrict__ in_i,
                              const float* __restrict__ in_h) {
    int idx = blockIdx.x * blockDim.x + threadIdx.x;        // float4 index
    const int total4 = BATCH * KX / 4;
    if (idx >= total4) return;
    int e = idx * 4;
    int b = e / KX;
    int k = e % KX;
    float4 v;
    if (k < IN_DIM) v = *(const float4*)(in_i + (size_t)b * IN_DIM + k);
    else            v = *(const float4*)(in_h + (size_t)b * HID + (k - IN_DIM));
    *(float4*)(g_x + e) = v;
}

// ---------------- fp32 GEMM, C[M,N] = A[M,K] @ W[N,K]^T ----------------
// W is selected from 4 stacked blocks of HID_BLOCK rows each (gate weights).
// Tiling: 128x128x16, 256 threads, 8x8 per thread, packed f32x2 FMA.
template <int GATE_SHIFT>
__device__ __forceinline__ void gemm_body(
    const float* __restrict__ A,
    const float* __restrict__ W0, const float* __restrict__ W1,
    const float* __restrict__ W2, const float* __restrict__ W3,
    float* __restrict__ C, int N, int K)
{
    constexpr int BM = 128, BN = 128, BK = 16;
    __shared__ __align__(16) float As[BK][BM];
    __shared__ __align__(16) float Bs[BK][BN];

    const int n0 = blockIdx.x * BN;
    const int m0 = blockIdx.y * BM;

    const int gate  = n0 >> GATE_SHIFT;
    const int nloc0 = n0 & ((1 << GATE_SHIFT) - 1);
    const float* Wsel = (gate == 0) ? W0 : (gate == 1) ? W1 : (gate == 2) ? W2 : W3;
    const float* Wbase = Wsel + (size_t)nloc0 * K;

    const int tid = threadIdx.x;
    const int tx = tid & 15;   // n direction (8 cols each)
    const int ty = tid >> 4;   // m direction (8 rows each)

    // accumulators: 8 rows x 4 f32x2-pairs (= 8 cols)
    unsigned long long acc[8][4];
#pragma unroll
    for (int i = 0; i < 8; i++)
#pragma unroll
        for (int j = 0; j < 4; j++) acc[i][j] = 0ull;

    const float* Aptr = A + (size_t)m0 * K;

    for (int k0 = 0; k0 < K; k0 += BK) {
        // A tile: 128x16 = 512 float4, 2 per thread
#pragma unroll
        for (int l = 0; l < 2; l++) {
            int f  = tid * 2 + l;
            int m  = f >> 2;
            int k4 = f & 3;
            float4 v = *(const float4*)(Aptr + (size_t)m * K + k0 + k4 * 4);
            As[k4 * 4 + 0][m] = v.x; As[k4 * 4 + 1][m] = v.y;
            As[k4 * 4 + 2][m] = v.z; As[k4 * 4 + 3][m] = v.w;
        }
        // W tile: 128x16
#pragma unroll
        for (int l = 0; l < 2; l++) {
            int f  = tid * 2 + l;
            int n  = f >> 2;
            int k4 = f & 3;
            float4 v = *(const float4*)(Wbase + (size_t)n * K + k0 + k4 * 4);
            Bs[k4 * 4 + 0][n] = v.x; Bs[k4 * 4 + 1][n] = v.y;
            Bs[k4 * 4 + 2][n] = v.z; Bs[k4 * 4 + 3][n] = v.w;
        }
        __syncthreads();

#pragma unroll
        for (int k = 0; k < BK; k++) {
            float a[8];
#pragma unroll
            for (int i = 0; i < 2; i++) {
                float4 av = *(const float4*)(&As[k][ty * 8 + i * 4]);
                a[i * 4 + 0] = av.x; a[i * 4 + 1] = av.y;
                a[i * 4 + 2] = av.z; a[i * 4 + 3] = av.w;
            }
            unsigned long long bq[4];
#pragma unroll
            for (int j = 0; j < 4; j++)
                bq[j] = *(const unsigned long long*)(&Bs[k][tx * 8 + j * 2]);

#pragma unroll
            for (int i = 0; i < 8; i++) {
                unsigned long long ap;
                unsigned int abits = __float_as_uint(a[i]);
                asm("mov.b64 %0, {%1, %1};" : "=l"(ap) : "r"(abits));
#pragma unroll
                for (int j = 0; j < 4; j++)
                    asm("fma.rn.f32x2 %0, %1, %2, %0;"
                        : "+l"(acc[i][j]) : "l"(ap), "l"(bq[j]));
            }
        }
        __syncthreads();
    }

    // store
#pragma unroll
    for (int i = 0; i < 8; i++) {
        int m = m0 + ty * 8 + i;
        float* crow = C + (size_t)m * N + n0 + tx * 8;
#pragma unroll
        for (int j = 0; j < 4; j++)
            *(unsigned long long*)(crow + j * 2) = acc[i][j];
    }
}

__global__ __launch_bounds__(256, 2)
void gemm_gates_kernel(const float* __restrict__ Wf, const float* __restrict__ Wi,
                       const float* __restrict__ Wc, const float* __restrict__ Wo)
{
    gemm_body<12>(g_x, Wf, Wi, Wc, Wo, g_gates, G4, KX);   // HID=4096 -> shift 12
}

__global__ __launch_bounds__(256, 2)
void gemm_out_kernel(const float* __restrict__ Wout)
{
    gemm_body<12>(g_ht, Wout, Wout, Wout, Wout, g_logits, OUT_DIM, HID); // n0<4096 -> gate 0
}

// ---------------- LSTM elementwise: gates -> it, ht, ct ----------------
__global__ void lstm_act_kernel(const float* __restrict__ cin,
                                const float* __restrict__ bf, const float* __restrict__ bi,
                                const float* __restrict__ bc, const float* __restrict__ bo,
                                float* __restrict__ out_it, float* __restrict__ out_ht,
                                float* __restrict__ out_ct)
{
    int idx = blockIdx.x * blockDim.x + threadIdx.x;
    if (idx >= BATCH * HID) return;
    int b = idx / HID;
    int j = idx - b * HID;
    const float* g = g_gates + (size_t)b * G4;
    float fp = g[j]           + bf[j];
    float ip = g[HID + j]     + bi[j];
    float cp = g[2 * HID + j] + bc[j];
    float op = g[3 * HID + j] + bo[j];
    float ft = 1.f / (1.f + __expf(-fp));
    float it = 1.f / (1.f + __expf(-ip));
    float cb = tanhf(cp);
    float ct = ft * cin[idx] + it * cb;
    float ot = 1.f / (1.f + __expf(-op));
    float ht = ot * tanhf(ct);
    out_it[idx] = it;
    out_ht[idx] = ht;
    out_ct[idx] = ct;
    g_ht[idx]   = ht;
}

// ---------------- log_softmax over rows of g_logits (+bout) ----------------
__global__ void logsoftmax_kernel(const float* __restrict__ bout,
                                  float* __restrict__ out)
{
    const int row = blockIdx.x;
    const float* x = g_logits + (size_t)row * OUT_DIM;
    float* y = out + (size_t)row * OUT_DIM;
    __shared__ float red[256];
    const int tid = threadIdx.x;

    float mx = -INFINITY;
    for (int j = tid; j < OUT_DIM; j += 256) mx = fmaxf(mx, x[j] + bout[j]);
    red[tid] = mx; __syncthreads();
    for (int s = 128; s > 0; s >>= 1) {
        if (tid < s) red[tid] = fmaxf(red[tid], red[tid + s]);
        __syncthreads();
    }
    mx = red[0];
    __syncthreads();

    float sum = 0.f;
    for (int j = tid; j < OUT_DIM; j += 256) sum += __expf(x[j] + bout[j] - mx);
    red[tid] = sum; __syncthreads();
    for (int s = 128; s > 0; s >>= 1) {
        if (tid < s) red[tid] += red[tid + s];
        __syncthreads();
    }
    float lse = mx + logf(red[0]);

    for (int j = tid; j < OUT_DIM; j += 256) y[j] = x[j] + bout[j] - lse;
}

// ---------------- launch ----------------
extern "C" void kernel_launch(void* const* d_in, const int* in_sizes, int n_in,
                              void* d_out, int out_size)
{
    const float* in_i  = (const float*)d_in[0];
    const float* in_h  = (const float*)d_in[1];
    const float* in_c  = (const float*)d_in[2];
    const float* Wf    = (const float*)d_in[3];
    const float* bf_   = (const float*)d_in[4];
    const float* Wi    = (const float*)d_in[5];
    const float* bi_   = (const float*)d_in[6];
    const float* Wc    = (const float*)d_in[7];
    const float* bc_   = (const float*)d_in[8];
    const float* Wo    = (const float*)d_in[9];
    const float* bo_   = (const float*)d_in[10];
    const float* Wout  = (const float*)d_in[11];
    const float* bout  = (const float*)d_in[12];

    float* out    = (float*)d_out;
    float* out_it = out;
    float* out_ht = out + (size_t)BATCH * HID;
    float* out_ct = out + 2 * (size_t)BATCH * HID;
    float* out_ls = out + 3 * (size_t)BATCH * HID;

    // 1) concat(i, h) -> g_x
    {
        int total4 = BATCH * KX / 4;
        concat_kernel<<<(total4 + 255) / 256, 256>>>(in_i, in_h);
    }
    // 2) gates = g_x @ [Wf;Wi;Wc;Wo]^T
    {
        dim3 grid(G4 / 128, BATCH / 128);
        gemm_gates_kernel<<<grid, 256>>>(Wf, Wi, Wc, Wo);
    }
    // 3) elementwise LSTM cell -> it, ht, ct (and g_ht scratch)
    {
        int total = BATCH * HID;
        lstm_act_kernel<<<(total + 255) / 256, 256>>>(in_c, bf_, bi_, bc_, bo_,
                                                      out_it, out_ht, out_ct);
    }
    // 4) logits = ht @ Wout^T
    {
        dim3 grid(OUT_DIM / 128, BATCH / 128);
        gemm_out_kernel<<<grid, 256>>>(Wout);
    }
    // 5) log_softmax(logits + bout) -> out
    logsoftmax_kernel<<<BATCH, 256>>>(bout, out_ls);
}

// round 9
// speedup vs baseline: 1.9457x; 1.9457x over previous
#include <cuda_runtime.h>
#include <cuda_bf16.h>
#include <mma.h>
#include <math.h>
#include <stdint.h>

using namespace nvcuda;

// Problem dims (fixed per reference)
#define BATCH   1024
#define IN_DIM  1024
#define HID     4096
#define KX      (IN_DIM + HID)   // 5120
#define G4      (4 * HID)        // 16384
#define OUT_DIM 4096

// ---------------- scratch (no cudaMalloc allowed) ----------------
// NOTE: these are ONLY referenced inside device code. Passing a __device__
// global as a host-side kernel argument hands the kernel the HOST shadow
// address (ATS makes that "work" by reading host zeros) — that was the
// rounds-3..8 bug.
__device__ __align__(16) __nv_bfloat16 g_xhi[BATCH * KX];
__device__ __align__(16) __nv_bfloat16 g_xlo[BATCH * KX];
__device__ __align__(16) __nv_bfloat16 g_whi[(size_t)G4 * KX];
__device__ __align__(16) __nv_bfloat16 g_wlo[(size_t)G4 * KX];
__device__ __align__(16) __nv_bfloat16 g_wouthi[(size_t)OUT_DIM * HID];
__device__ __align__(16) __nv_bfloat16 g_woutlo[(size_t)OUT_DIM * HID];
__device__ __align__(16) __nv_bfloat16 g_hthi[BATCH * HID];
__device__ __align__(16) __nv_bfloat16 g_htlo[BATCH * HID];
__device__ float g_gates[(size_t)BATCH * G4];
__device__ float g_logits[(size_t)BATCH * OUT_DIM];

// ---------------- fp32 -> bf16 hi/lo converters ----------------
__device__ __forceinline__ void split1(float v, __nv_bfloat16* hi, __nv_bfloat16* lo) {
    __nv_bfloat16 h = __float2bfloat16(v);
    *hi = h;
    *lo = __float2bfloat16(v - __bfloat162float(h));
}

__global__ void convert_x_kernel(const float* __restrict__ i_, const float* __restrict__ h_) {
    const int b = blockIdx.x;                 // one batch row per block
    for (int k = threadIdx.x; k < KX; k += blockDim.x) {
        float v = (k < IN_DIM) ? i_[(size_t)b * IN_DIM + k]
                               : h_[(size_t)b * HID + (k - IN_DIM)];
        split1(v, &g_xhi[(size_t)b * KX + k], &g_xlo[(size_t)b * KX + k]);
    }
}

__global__ void convert_w_kernel(const float* __restrict__ Wf, const float* __restrict__ Wi,
                                 const float* __restrict__ Wc, const float* __restrict__ Wo) {
    const int n = blockIdx.x;                 // stacked weight row (0..16383)
    const int gate = n >> 12;                 // /HID
    const int nl = n & (HID - 1);
    const float* src = (gate == 0) ? Wf : (gate == 1) ? Wi : (gate == 2) ? Wc : Wo;
    const float* row = src + (size_t)nl * KX;
    __nv_bfloat16* hi = g_whi + (size_t)n * KX;
    __nv_bfloat16* lo = g_wlo + (size_t)n * KX;
    for (int k = threadIdx.x; k < KX; k += blockDim.x)
        split1(row[k], &hi[k], &lo[k]);
}

__global__ void convert_wout_kernel(const float* __restrict__ W) {
    const int n = blockIdx.x;                 // row (0..4095)
    const float* row = W + (size_t)n * HID;
    __nv_bfloat16* hi = g_wouthi + (size_t)n * HID;
    __nv_bfloat16* lo = g_woutlo + (size_t)n * HID;
    for (int k = threadIdx.x; k < HID; k += blockDim.x)
        split1(row[k], &hi[k], &lo[k]);
}

// ---------------- wmma split-bf16 GEMM: C[M,N] = A[M,K] @ W[N,K]^T ----------------
// C = Ahi*Whi + Ahi*Wlo + Alo*Whi  (fp32 accum, wmma 16x16x16 bf16).
// PASS_ID 0: gates = x @ Wall^T   PASS_ID 1: logits = ht @ Wout^T
// All scratch arrays bound INSIDE device code (true device addresses).
#define WLD 40   // smem leading dim in elements (mult of 8; dodges conflicts)

template <int PASS_ID>
__global__ __launch_bounds__(256)
void gemm_wmma_kernel()
{
    constexpr int N = (PASS_ID == 0) ? G4 : OUT_DIM;
    constexpr int K = (PASS_ID == 0) ? KX : HID;
    const __nv_bfloat16* __restrict__ Ahi = (PASS_ID == 0) ? g_xhi : g_hthi;
    const __nv_bfloat16* __restrict__ Alo = (PASS_ID == 0) ? g_xlo : g_htlo;
    const __nv_bfloat16* __restrict__ Whi = (PASS_ID == 0) ? g_whi : g_wouthi;
    const __nv_bfloat16* __restrict__ Wlo = (PASS_ID == 0) ? g_wlo : g_woutlo;
    float* __restrict__ C = (PASS_ID == 0) ? g_gates : g_logits;

    __shared__ __align__(16) __nv_bfloat16 sAh[128 * WLD];
    __shared__ __align__(16) __nv_bfloat16 sAl[128 * WLD];
    __shared__ __align__(16) __nv_bfloat16 sWh[128 * WLD];
    __shared__ __align__(16) __nv_bfloat16 sWl[128 * WLD];

    const int tid  = threadIdx.x;
    const int wid  = tid >> 5;
    const int warp_m = wid & 3;    // 4 warps over M, 32 rows each
    const int warp_n = wid >> 2;   // 2 warps over N, 64 cols each

    const int m0 = blockIdx.x * 128;
    const int n0 = blockIdx.y * 128;

    // loader mapping: 512 16B-chunks per matrix; thread handles chunks tid, tid+256
    const int rA = tid >> 2,         cA = tid & 3;
    const int rB = (tid + 256) >> 2, cB = (tid + 256) & 3;

    const __nv_bfloat16* pAh0 = Ahi + (size_t)(m0 + rA) * K + cA * 8;
    const __nv_bfloat16* pAh1 = Ahi + (size_t)(m0 + rB) * K + cB * 8;
    const __nv_bfloat16* pAl0 = Alo + (size_t)(m0 + rA) * K + cA * 8;
    const __nv_bfloat16* pAl1 = Alo + (size_t)(m0 + rB) * K + cB * 8;
    const __nv_bfloat16* pWh0 = Whi + (size_t)(n0 + rA) * K + cA * 8;
    const __nv_bfloat16* pWh1 = Whi + (size_t)(n0 + rB) * K + cB * 8;
    const __nv_bfloat16* pWl0 = Wlo + (size_t)(n0 + rA) * K + cA * 8;
    const __nv_bfloat16* pWl1 = Wlo + (size_t)(n0 + rB) * K + cB * 8;

    const uint32_t s0 = (uint32_t)(rA * WLD + cA * 8);
    const uint32_t s1 = (uint32_t)(rB * WLD + cB * 8);

    wmma::fragment<wmma::accumulator, 16, 16, 16, float> acc[2][4];
#pragma unroll
    for (int i = 0; i < 2; i++)
#pragma unroll
        for (int j = 0; j < 4; j++) wmma::fill_fragment(acc[i][j], 0.0f);

    uint4 buf[8];
    auto load_buf = [&](int k0) {
        buf[0] = *(const uint4*)(pAh0 + k0);
        buf[1] = *(const uint4*)(pAh1 + k0);
        buf[2] = *(const uint4*)(pAl0 + k0);
        buf[3] = *(const uint4*)(pAl1 + k0);
        buf[4] = *(const uint4*)(pWh0 + k0);
        buf[5] = *(const uint4*)(pWh1 + k0);
        buf[6] = *(const uint4*)(pWl0 + k0);
        buf[7] = *(const uint4*)(pWl1 + k0);
    };

    load_buf(0);

    for (int k0 = 0; k0 < K; k0 += 32) {
        __syncthreads();   // previous compute done before smem overwrite
        *(uint4*)(sAh + s0) = buf[0];
        *(uint4*)(sAh + s1) = buf[1];
        *(uint4*)(sAl + s0) = buf[2];
        *(uint4*)(sAl + s1) = buf[3];
        *(uint4*)(sWh + s0) = buf[4];
        *(uint4*)(sWh + s1) = buf[5];
        *(uint4*)(sWl + s0) = buf[6];
        *(uint4*)(sWl + s1) = buf[7];
        __syncthreads();
        if (k0 + 32 < K) load_buf(k0 + 32);   // overlaps with compute below

#pragma unroll
        for (int kk = 0; kk < 32; kk += 16) {
            wmma::fragment<wmma::matrix_a, 16, 16, 16, __nv_bfloat16, wmma::row_major> fah[2], fal[2];
#pragma unroll
            for (int i = 0; i < 2; i++) {
                wmma::load_matrix_sync(fah[i], &sAh[(warp_m * 32 + i * 16) * WLD + kk], WLD);
                wmma::load_matrix_sync(fal[i], &sAl[(warp_m * 32 + i * 16) * WLD + kk], WLD);
            }
#pragma unroll
            for (int j4 = 0; j4 < 2; ++j4) {   // two halves of the 4 n-frags (reg liveness)
                wmma::fragment<wmma::matrix_b, 16, 16, 16, __nv_bfloat16, wmma::col_major> fbh[2], fbl[2];
#pragma unroll
                for (int j = 0; j < 2; j++) {
                    const int nf = warp_n * 64 + (j4 * 2 + j) * 16;
                    wmma::load_matrix_sync(fbh[j], &sWh[nf * WLD + kk], WLD);
                    wmma::load_matrix_sync(fbl[j], &sWl[nf * WLD + kk], WLD);
                }
#pragma unroll
                for (int j = 0; j < 2; j++)
#pragma unroll
                    for (int i = 0; i < 2; i++)
                        wmma::mma_sync(acc[i][j4 * 2 + j], fah[i], fbh[j], acc[i][j4 * 2 + j]);
#pragma unroll
                for (int j = 0; j < 2; j++)
#pragma unroll
                    for (int i = 0; i < 2; i++)
                        wmma::mma_sync(acc[i][j4 * 2 + j], fah[i], fbl[j], acc[i][j4 * 2 + j]);
#pragma unroll
                for (int j = 0; j < 2; j++)
#pragma unroll
                    for (int i = 0; i < 2; i++)
                        wmma::mma_sync(acc[i][j4 * 2 + j], fal[i], fbh[j], acc[i][j4 * 2 + j]);
            }
        }
    }

#pragma unroll
    for (int i = 0; i < 2; i++)
#pragma unroll
        for (int j = 0; j < 4; j++) {
            float* p = C + (size_t)(m0 + warp_m * 32 + i * 16) * N + n0 + warp_n * 64 + j * 16;
            wmma::store_matrix_sync(p, acc[i][j], N, wmma::mem_row_major);
        }
}

// ---------------- LSTM elementwise: gates -> it, ht, ct (+ ht hi/lo split) ----------------
__global__ void lstm_act_kernel(const float* __restrict__ cin,
                                const float* __restrict__ bf, const float* __restrict__ bi,
                                const float* __restrict__ bc, const float* __restrict__ bo,
                                float* __restrict__ out_it, float* __restrict__ out_ht,
                                float* __restrict__ out_ct)
{
    int idx = blockIdx.x * blockDim.x + threadIdx.x;
    if (idx >= BATCH * HID) return;
    int b = idx / HID;
    int j = idx - b * HID;
    const float* g = g_gates + (size_t)b * G4;
    float fp = g[j]           + bf[j];
    float ip = g[HID + j]     + bi[j];
    float cp = g[2 * HID + j] + bc[j];
    float op = g[3 * HID + j] + bo[j];
    float ft = 1.f / (1.f + __expf(-fp));
    float it = 1.f / (1.f + __expf(-ip));
    float cb = tanhf(cp);
    float ct = ft * cin[idx] + it * cb;
    float ot = 1.f / (1.f + __expf(-op));
    float ht = ot * tanhf(ct);
    out_it[idx] = it;
    out_ht[idx] = ht;
    out_ct[idx] = ct;
    __nv_bfloat16 hh = __float2bfloat16(ht);
    g_hthi[idx] = hh;
    g_htlo[idx] = __float2bfloat16(ht - __bfloat162float(hh));
}

// ---------------- log_softmax over rows of g_logits (+bout) ----------------
__global__ void logsoftmax_kernel(const float* __restrict__ bout,
                                  float* __restrict__ out)
{
    const int row = blockIdx.x;
    const float* x = g_logits + (size_t)row * OUT_DIM;
    float* y = out + (size_t)row * OUT_DIM;
    __shared__ float red[256];
    const int tid = threadIdx.x;

    float mx = -INFINITY;
    for (int j = tid; j < OUT_DIM; j += 256) mx = fmaxf(mx, x[j] + bout[j]);
    red[tid] = mx; __syncthreads();
    for (int s = 128; s > 0; s >>= 1) {
        if (tid < s) red[tid] = fmaxf(red[tid], red[tid + s]);
        __syncthreads();
    }
    mx = red[0];
    __syncthreads();

    float sum = 0.f;
    for (int j = tid; j < OUT_DIM; j += 256) sum += __expf(x[j] + bout[j] - mx);
    red[tid] = sum; __syncthreads();
    for (int s = 128; s > 0; s >>= 1) {
        if (tid < s) red[tid] += red[tid + s];
        __syncthreads();
    }
    float lse = mx + logf(red[0]);

    for (int j = tid; j < OUT_DIM; j += 256) y[j] = x[j] + bout[j] - lse;
}

// ---------------- launch ----------------
extern "C" void kernel_launch(void* const* d_in, const int* in_sizes, int n_in,
                              void* d_out, int out_size)
{
    const float* in_i  = (const float*)d_in[0];
    const float* in_h  = (const float*)d_in[1];
    const float* in_c  = (const float*)d_in[2];
    const float* Wf    = (const float*)d_in[3];
    const float* bf_   = (const float*)d_in[4];
    const float* Wi    = (const float*)d_in[5];
    const float* bi_   = (const float*)d_in[6];
    const float* Wc    = (const float*)d_in[7];
    const float* bc_   = (const float*)d_in[8];
    const float* Wo    = (const float*)d_in[9];
    const float* bo_   = (const float*)d_in[10];
    const float* Wout  = (const float*)d_in[11];
    const float* bout  = (const float*)d_in[12];

    float* out    = (float*)d_out;
    float* out_it = out;
    float* out_ht = out + (size_t)BATCH * HID;
    float* out_ct = out + 2 * (size_t)BATCH * HID;
    float* out_ls = out + 3 * (size_t)BATCH * HID;

    // 1) fp32 -> bf16 hi/lo conversions (write device globals from device code)
    convert_x_kernel<<<BATCH, 256>>>(in_i, in_h);
    convert_w_kernel<<<G4, 256>>>(Wf, Wi, Wc, Wo);
    convert_wout_kernel<<<OUT_DIM, 256>>>(Wout);

    // 2) gates = x @ [Wf;Wi;Wc;Wo]^T  (split-bf16 wmma; scratch bound in-kernel)
    {
        dim3 grid(BATCH / 128, G4 / 128);
        gemm_wmma_kernel<0><<<grid, 256>>>();
    }

    // 3) elementwise LSTM cell -> it, ht, ct (+ ht split)
    {
        int total = BATCH * HID;
        lstm_act_kernel<<<(total + 255) / 256, 256>>>(in_c, bf_, bi_, bc_, bo_,
                                                      out_it, out_ht, out_ct);
    }

    // 4) logits = ht @ Wout^T
    {
        dim3 grid(BATCH / 128, OUT_DIM / 128);
        gemm_wmma_kernel<1><<<grid, 256>>>();
    }

    // 5) log_softmax(logits + bout) -> out
    logsoftmax_kernel<<<BATCH, 256>>>(bout, out_ls);
}

// round 10
// speedup vs baseline: 2.1192x; 1.0891x over previous
#include <cuda_runtime.h>
#include <cuda_bf16.h>
#include <mma.h>
#include <math.h>
#include <stdint.h>

using namespace nvcuda;

// Problem dims (fixed per reference)
#define BATCH   1024
#define IN_DIM  1024
#define HID     4096
#define KX      (IN_DIM + HID)   // 5120
#define G4      (4 * HID)        // 16384
#define OUT_DIM 4096

// ---------------- scratch (no cudaMalloc allowed) ----------------
// Referenced ONLY inside device code (host-side use would get the host shadow).
__device__ __align__(16) __nv_bfloat16 g_xhi[BATCH * KX];
__device__ __align__(16) __nv_bfloat16 g_xlo[BATCH * KX];
__device__ __align__(16) __nv_bfloat16 g_whi[(size_t)G4 * KX];
__device__ __align__(16) __nv_bfloat16 g_wlo[(size_t)G4 * KX];
__device__ __align__(16) __nv_bfloat16 g_wouthi[(size_t)OUT_DIM * HID];
__device__ __align__(16) __nv_bfloat16 g_woutlo[(size_t)OUT_DIM * HID];
__device__ __align__(16) __nv_bfloat16 g_hthi[BATCH * HID];
__device__ __align__(16) __nv_bfloat16 g_htlo[BATCH * HID];
__device__ float g_gates[(size_t)BATCH * G4];
__device__ float g_logits[(size_t)BATCH * OUT_DIM];

// ---------------- PTX helpers ----------------
__device__ __forceinline__ uint32_t smem_u32(const void* p) {
    uint32_t a;
    asm("{ .reg .u64 t; cvta.to.shared.u64 t, %1; cvt.u32.u64 %0, t; }" : "=r"(a) : "l"(p));
    return a;
}
__device__ __forceinline__ void cp16(uint32_t s, const void* g) {
    asm volatile("cp.async.cg.shared.global [%0], [%1], 16;" :: "r"(s), "l"(g) : "memory");
}
__device__ __forceinline__ void cp_commit() {
    asm volatile("cp.async.commit_group;" ::: "memory");
}
__device__ __forceinline__ void cp_wait1() {
    asm volatile("cp.async.wait_group 1;" ::: "memory");
}

// ---------------- fp32 -> bf16 hi/lo conversion (vectorized) ----------------
__device__ __forceinline__ void split4_store(float4 v, __nv_bfloat16* hi, __nv_bfloat16* lo) {
    float vv[4] = {v.x, v.y, v.z, v.w};
    uint32_t hw[2], lw[2];
#pragma unroll
    for (int p = 0; p < 2; p++) {
        __nv_bfloat16 h0 = __float2bfloat16(vv[2 * p]);
        __nv_bfloat16 h1 = __float2bfloat16(vv[2 * p + 1]);
        __nv_bfloat16 l0 = __float2bfloat16(vv[2 * p]     - __bfloat162float(h0));
        __nv_bfloat16 l1 = __float2bfloat16(vv[2 * p + 1] - __bfloat162float(h1));
        hw[p] = (uint32_t)__bfloat16_as_ushort(h0) | ((uint32_t)__bfloat16_as_ushort(h1) << 16);
        lw[p] = (uint32_t)__bfloat16_as_ushort(l0) | ((uint32_t)__bfloat16_as_ushort(l1) << 16);
    }
    *(uint2*)hi = make_uint2(hw[0], hw[1]);
    *(uint2*)lo = make_uint2(lw[0], lw[1]);
}

__global__ void convert_x_kernel(const float* __restrict__ i_, const float* __restrict__ h_) {
    const int b = blockIdx.x;
    for (int k4 = threadIdx.x; k4 < KX / 4; k4 += blockDim.x) {
        int k = k4 * 4;
        float4 v = (k < IN_DIM) ? *(const float4*)(i_ + (size_t)b * IN_DIM + k)
                                : *(const float4*)(h_ + (size_t)b * HID + (k - IN_DIM));
        split4_store(v, &g_xhi[(size_t)b * KX + k], &g_xlo[(size_t)b * KX + k]);
    }
}

__global__ void convert_w_kernel(const float* __restrict__ Wf, const float* __restrict__ Wi,
                                 const float* __restrict__ Wc, const float* __restrict__ Wo) {
    const int n = blockIdx.x;                 // stacked weight row (0..16383)
    const int gate = n >> 12;
    const int nl = n & (HID - 1);
    const float* src = (gate == 0) ? Wf : (gate == 1) ? Wi : (gate == 2) ? Wc : Wo;
    const float* row = src + (size_t)nl * KX;
    __nv_bfloat16* hi = g_whi + (size_t)n * KX;
    __nv_bfloat16* lo = g_wlo + (size_t)n * KX;
    for (int k4 = threadIdx.x; k4 < KX / 4; k4 += blockDim.x) {
        int k = k4 * 4;
        split4_store(*(const float4*)(row + k), &hi[k], &lo[k]);
    }
}

__global__ void convert_wout_kernel(const float* __restrict__ W) {
    const int n = blockIdx.x;
    const float* row = W + (size_t)n * HID;
    __nv_bfloat16* hi = g_wouthi + (size_t)n * HID;
    __nv_bfloat16* lo = g_woutlo + (size_t)n * HID;
    for (int k4 = threadIdx.x; k4 < HID / 4; k4 += blockDim.x) {
        int k = k4 * 4;
        split4_store(*(const float4*)(row + k), &hi[k], &lo[k]);
    }
}

// ---------------- wmma split-bf16 GEMM: C[M,N] = A[M,K] @ W[N,K]^T ----------------
// C = Ahi*Whi + Ahi*Wlo + Alo*Whi  (fp32 accum, wmma 16x16x16 bf16).
// CTA 128x128, k-step 32, 8 warps (4M x 2N).
// 3-stage cp.async pipeline, loads issued 2 iters ahead, ONE barrier per iter.
#define WLD   40                      // smem leading dim (elements); 80 B rows
#define MATEL (128 * WLD)             // elements per matrix buffer (10240 B)
#define STEL  (4 * MATEL)             // elements per stage: [Ah][Al][Wh][Wl]

template <int PASS_ID>
__global__ __launch_bounds__(256)
void gemm_wmma_kernel()
{
    constexpr int N = (PASS_ID == 0) ? G4 : OUT_DIM;
    constexpr int K = (PASS_ID == 0) ? KX : HID;
    const __nv_bfloat16* __restrict__ Ahi = (PASS_ID == 0) ? g_xhi : g_hthi;
    const __nv_bfloat16* __restrict__ Alo = (PASS_ID == 0) ? g_xlo : g_htlo;
    const __nv_bfloat16* __restrict__ Whi = (PASS_ID == 0) ? g_whi : g_wouthi;
    const __nv_bfloat16* __restrict__ Wlo = (PASS_ID == 0) ? g_wlo : g_woutlo;
    float* __restrict__ C = (PASS_ID == 0) ? g_gates : g_logits;

    extern __shared__ __align__(16) __nv_bfloat16 smem[];   // 3 * STEL elements
    const uint32_t sbase = smem_u32(smem);

    const int tid  = threadIdx.x;
    const int wid  = tid >> 5;
    const int warp_m = wid & 3;    // 4 warps over M, 32 rows each
    const int warp_n = wid >> 2;   // 2 warps over N, 64 cols each

    const int m0 = blockIdx.x * 128;
    const int n0 = blockIdx.y * 128;
    const int niter = K / 32;

    // producer mapping: 512 16B-chunks per matrix; thread handles chunks tid, tid+256
    const int rA = tid >> 2,         cA = tid & 3;
    const int rB = (tid + 256) >> 2, cB = (tid + 256) & 3;

    const __nv_bfloat16* pAh0 = Ahi + (size_t)(m0 + rA) * K + cA * 8;
    const __nv_bfloat16* pAh1 = Ahi + (size_t)(m0 + rB) * K + cB * 8;
    const __nv_bfloat16* pAl0 = Alo + (size_t)(m0 + rA) * K + cA * 8;
    const __nv_bfloat16* pAl1 = Alo + (size_t)(m0 + rB) * K + cB * 8;
    const __nv_bfloat16* pWh0 = Whi + (size_t)(n0 + rA) * K + cA * 8;
    const __nv_bfloat16* pWh1 = Whi + (size_t)(n0 + rB) * K + cB * 8;
    const __nv_bfloat16* pWl0 = Wlo + (size_t)(n0 + rA) * K + cA * 8;
    const __nv_bfloat16* pWl1 = Wlo + (size_t)(n0 + rB) * K + cB * 8;

    const uint32_t s0 = (uint32_t)(rA * WLD + cA * 8) * 2;   // byte offsets
    const uint32_t s1 = (uint32_t)(rB * WLD + cB * 8) * 2;

    auto issue_stage = [&](int stage, int it) {
        const uint32_t st = sbase + (uint32_t)(stage * STEL) * 2;
        const int k0 = it * 32;
        cp16(st + s0,                 pAh0 + k0);
        cp16(st + s1,                 pAh1 + k0);
        cp16(st + MATEL * 2 + s0,     pAl0 + k0);
        cp16(st + MATEL * 2 + s1,     pAl1 + k0);
        cp16(st + 2 * MATEL * 2 + s0, pWh0 + k0);
        cp16(st + 2 * MATEL * 2 + s1, pWh1 + k0);
        cp16(st + 3 * MATEL * 2 + s0, pWl0 + k0);
        cp16(st + 3 * MATEL * 2 + s1, pWl1 + k0);
    };

    wmma::fragment<wmma::accumulator, 16, 16, 16, float> acc[2][4];
#pragma unroll
    for (int i = 0; i < 2; i++)
#pragma unroll
        for (int j = 0; j < 4; j++) wmma::fill_fragment(acc[i][j], 0.0f);

    // prologue: stages 0 and 1 in flight
    issue_stage(0, 0); cp_commit();
    issue_stage(1, 1); cp_commit();

    int stage = 0;
    for (int it = 0; it < niter; ++it) {
        cp_wait1();        // group for `it` done (group it+1 may be pending)
        __syncthreads();   // all warps see stage data; stage (it+2)%3 free of readers

        if (it + 2 < niter) issue_stage((stage + 2) % 3, it + 2);
        cp_commit();       // exactly one group per iteration (may be empty)

        const __nv_bfloat16* sAh = smem + stage * STEL;
        const __nv_bfloat16* sAl = sAh + MATEL;
        const __nv_bfloat16* sWh = sAh + 2 * MATEL;
        const __nv_bfloat16* sWl = sAh + 3 * MATEL;

#pragma unroll
        for (int kk = 0; kk < 32; kk += 16) {
            wmma::fragment<wmma::matrix_a, 16, 16, 16, __nv_bfloat16, wmma::row_major> fah[2], fal[2];
#pragma unroll
            for (int i = 0; i < 2; i++) {
                wmma::load_matrix_sync(fah[i], &sAh[(warp_m * 32 + i * 16) * WLD + kk], WLD);
                wmma::load_matrix_sync(fal[i], &sAl[(warp_m * 32 + i * 16) * WLD + kk], WLD);
            }
#pragma unroll
            for (int j4 = 0; j4 < 2; ++j4) {   // two halves of 4 n-frags (reg liveness)
                wmma::fragment<wmma::matrix_b, 16, 16, 16, __nv_bfloat16, wmma::col_major> fbh[2], fbl[2];
#pragma unroll
                for (int j = 0; j < 2; j++) {
                    const int nf = warp_n * 64 + (j4 * 2 + j) * 16;
                    wmma::load_matrix_sync(fbh[j], &sWh[nf * WLD + kk], WLD);
                    wmma::load_matrix_sync(fbl[j], &sWl[nf * WLD + kk], WLD);
                }
#pragma unroll
                for (int j = 0; j < 2; j++)
#pragma unroll
                    for (int i = 0; i < 2; i++)
                        wmma::mma_sync(acc[i][j4 * 2 + j], fah[i], fbh[j], acc[i][j4 * 2 + j]);
#pragma unroll
                for (int j = 0; j < 2; j++)
#pragma unroll
                    for (int i = 0; i < 2; i++)
                        wmma::mma_sync(acc[i][j4 * 2 + j], fah[i], fbl[j], acc[i][j4 * 2 + j]);
#pragma unroll
                for (int j = 0; j < 2; j++)
#pragma unroll
                    for (int i = 0; i < 2; i++)
                        wmma::mma_sync(acc[i][j4 * 2 + j], fal[i], fbh[j], acc[i][j4 * 2 + j]);
            }
        }
        stage = (stage + 1) % 3;
    }

#pragma unroll
    for (int i = 0; i < 2; i++)
#pragma unroll
        for (int j = 0; j < 4; j++) {
            float* p = C + (size_t)(m0 + warp_m * 32 + i * 16) * N + n0 + warp_n * 64 + j * 16;
            wmma::store_matrix_sync(p, acc[i][j], N, wmma::mem_row_major);
        }
}

// ---------------- LSTM elementwise ----------------
__global__ void lstm_act_kernel(const float* __restrict__ cin,
                                const float* __restrict__ bf, const float* __restrict__ bi,
                                const float* __restrict__ bc, const float* __restrict__ bo,
                                float* __restrict__ out_it, float* __restrict__ out_ht,
                                float* __restrict__ out_ct)
{
    int idx = blockIdx.x * blockDim.x + threadIdx.x;
    if (idx >= BATCH * HID) return;
    int b = idx / HID;
    int j = idx - b * HID;
    const float* g = g_gates + (size_t)b * G4;
    float fp = g[j]           + bf[j];
    float ip = g[HID + j]     + bi[j];
    float cp = g[2 * HID + j] + bc[j];
    float op = g[3 * HID + j] + bo[j];
    float ft = 1.f / (1.f + __expf(-fp));
    float it = 1.f / (1.f + __expf(-ip));
    float cb = tanhf(cp);
    float ct = ft * cin[idx] + it * cb;
    float ot = 1.f / (1.f + __expf(-op));
    float ht = ot * tanhf(ct);
    out_it[idx] = it;
    out_ht[idx] = ht;
    out_ct[idx] = ct;
    __nv_bfloat16 hh = __float2bfloat16(ht);
    g_hthi[idx] = hh;
    g_htlo[idx] = __float2bfloat16(ht - __bfloat162float(hh));
}

// ---------------- log_softmax ----------------
__global__ void logsoftmax_kernel(const float* __restrict__ bout,
                                  float* __restrict__ out)
{
    const int row = blockIdx.x;
    const float* x = g_logits + (size_t)row * OUT_DIM;
    float* y = out + (size_t)row * OUT_DIM;
    __shared__ float red[256];
    const int tid = threadIdx.x;

    float mx = -INFINITY;
    for (int j = tid; j < OUT_DIM; j += 256) mx = fmaxf(mx, x[j] + bout[j]);
    red[tid] = mx; __syncthreads();
    for (int s = 128; s > 0; s >>= 1) {
        if (tid < s) red[tid] = fmaxf(red[tid], red[tid + s]);
        __syncthreads();
    }
    mx = red[0];
    __syncthreads();

    float sum = 0.f;
    for (int j = tid; j < OUT_DIM; j += 256) sum += __expf(x[j] + bout[j] - mx);
    red[tid] = sum; __syncthreads();
    for (int s = 128; s > 0; s >>= 1) {
        if (tid < s) red[tid] += red[tid + s];
        __syncthreads();
    }
    float lse = mx + logf(red[0]);

    for (int j = tid; j < OUT_DIM; j += 256) y[j] = x[j] + bout[j] - lse;
}

// ---------------- launch ----------------
extern "C" void kernel_launch(void* const* d_in, const int* in_sizes, int n_in,
                              void* d_out, int out_size)
{
    const float* in_i  = (const float*)d_in[0];
    const float* in_h  = (const float*)d_in[1];
    const float* in_c  = (const float*)d_in[2];
    const float* Wf    = (const float*)d_in[3];
    const float* bf_   = (const float*)d_in[4];
    const float* Wi    = (const float*)d_in[5];
    const float* bi_   = (const float*)d_in[6];
    const float* Wc    = (const float*)d_in[7];
    const float* bc_   = (const float*)d_in[8];
    const float* Wo    = (const float*)d_in[9];
    const float* bo_   = (const float*)d_in[10];
    const float* Wout  = (const float*)d_in[11];
    const float* bout  = (const float*)d_in[12];

    float* out    = (float*)d_out;
    float* out_it = out;
    float* out_ht = out + (size_t)BATCH * HID;
    float* out_ct = out + 2 * (size_t)BATCH * HID;
    float* out_ls = out + 3 * (size_t)BATCH * HID;

    const int SMEM_DYN = 3 * STEL * 2;   // 3 stages * 40960 B = 122880
    cudaFuncSetAttribute(gemm_wmma_kernel<0>,
                         cudaFuncAttributeMaxDynamicSharedMemorySize, SMEM_DYN);
    cudaFuncSetAttribute(gemm_wmma_kernel<1>,
                         cudaFuncAttributeMaxDynamicSharedMemorySize, SMEM_DYN);

    // 1) fp32 -> bf16 hi/lo conversions (vectorized)
    convert_x_kernel<<<BATCH, 256>>>(in_i, in_h);
    convert_w_kernel<<<G4, 256>>>(Wf, Wi, Wc, Wo);
    convert_wout_kernel<<<OUT_DIM, 256>>>(Wout);

    // 2) gates = x @ [Wf;Wi;Wc;Wo]^T
    {
        dim3 grid(BATCH / 128, G4 / 128);
        gemm_wmma_kernel<0><<<grid, 256, SMEM_DYN>>>();
    }

    // 3) elementwise LSTM cell -> it, ht, ct (+ ht split)
    {
        int total = BATCH * HID;
        lstm_act_kernel<<<(total + 255) / 256, 256>>>(in_c, bf_, bi_, bc_, bo_,
                                                      out_it, out_ht, out_ct);
    }

    // 4) logits = ht @ Wout^T
    {
        dim3 grid(BATCH / 128, OUT_DIM / 128);
        gemm_wmma_kernel<1><<<grid, 256, SMEM_DYN>>>();
    }

    // 5) log_softmax(logits + bout) -> out
    logsoftmax_kernel<<<BATCH, 256>>>(bout, out_ls);
}

// round 11
// speedup vs baseline: 2.2240x; 1.0495x over previous
#include <cuda_runtime.h>
#include <cuda_bf16.h>
#include <mma.h>
#include <math.h>
#include <stdint.h>

using namespace nvcuda;

// Problem dims (fixed per reference)
#define BATCH   1024
#define IN_DIM  1024
#define HID     4096
#define KX      (IN_DIM + HID)   // 5120
#define G4      (4 * HID)        // 16384
#define OUT_DIM 4096

// ---------------- scratch (no cudaMalloc allowed) ----------------
// Referenced ONLY inside device code (host-side use would get the host shadow).
__device__ __align__(16) __nv_bfloat16 g_xhi[BATCH * KX];
__device__ __align__(16) __nv_bfloat16 g_xlo[BATCH * KX];
__device__ __align__(16) __nv_bfloat16 g_whi[(size_t)G4 * KX];
__device__ __align__(16) __nv_bfloat16 g_wlo[(size_t)G4 * KX];
__device__ __align__(16) __nv_bfloat16 g_wouthi[(size_t)OUT_DIM * HID];
__device__ __align__(16) __nv_bfloat16 g_woutlo[(size_t)OUT_DIM * HID];
__device__ __align__(16) __nv_bfloat16 g_hthi[BATCH * HID];
__device__ __align__(16) __nv_bfloat16 g_htlo[BATCH * HID];
__device__ float g_gates[(size_t)BATCH * G4];
__device__ float g_logits[(size_t)BATCH * OUT_DIM];

// ---------------- PTX helpers ----------------
__device__ __forceinline__ uint32_t smem_u32(const void* p) {
    uint32_t a;
    asm("{ .reg .u64 t; cvta.to.shared.u64 t, %1; cvt.u32.u64 %0, t; }" : "=r"(a) : "l"(p));
    return a;
}
__device__ __forceinline__ void cp16(uint32_t s, const void* g) {
    asm volatile("cp.async.cg.shared.global [%0], [%1], 16;" :: "r"(s), "l"(g) : "memory");
}
__device__ __forceinline__ void cp_commit() {
    asm volatile("cp.async.commit_group;" ::: "memory");
}
__device__ __forceinline__ void cp_wait1() {
    asm volatile("cp.async.wait_group 1;" ::: "memory");
}

// ---------------- fp32 -> bf16 hi/lo conversion (vectorized) ----------------
__device__ __forceinline__ void split4_store(float4 v, __nv_bfloat16* hi, __nv_bfloat16* lo) {
    float vv[4] = {v.x, v.y, v.z, v.w};
    uint32_t hw[2], lw[2];
#pragma unroll
    for (int p = 0; p < 2; p++) {
        __nv_bfloat16 h0 = __float2bfloat16(vv[2 * p]);
        __nv_bfloat16 h1 = __float2bfloat16(vv[2 * p + 1]);
        __nv_bfloat16 l0 = __float2bfloat16(vv[2 * p]     - __bfloat162float(h0));
        __nv_bfloat16 l1 = __float2bfloat16(vv[2 * p + 1] - __bfloat162float(h1));
        hw[p] = (uint32_t)__bfloat16_as_ushort(h0) | ((uint32_t)__bfloat16_as_ushort(h1) << 16);
        lw[p] = (uint32_t)__bfloat16_as_ushort(l0) | ((uint32_t)__bfloat16_as_ushort(l1) << 16);
    }
    *(uint2*)hi = make_uint2(hw[0], hw[1]);
    *(uint2*)lo = make_uint2(lw[0], lw[1]);
}

__global__ void convert_x_kernel(const float* __restrict__ i_, const float* __restrict__ h_) {
    const int b = blockIdx.x;
    for (int k4 = threadIdx.x; k4 < KX / 4; k4 += blockDim.x) {
        int k = k4 * 4;
        float4 v = (k < IN_DIM) ? *(const float4*)(i_ + (size_t)b * IN_DIM + k)
                                : *(const float4*)(h_ + (size_t)b * HID + (k - IN_DIM));
        split4_store(v, &g_xhi[(size_t)b * KX + k], &g_xlo[(size_t)b * KX + k]);
    }
}

__global__ void convert_w_kernel(const float* __restrict__ Wf, const float* __restrict__ Wi,
                                 const float* __restrict__ Wc, const float* __restrict__ Wo) {
    const int n = blockIdx.x;                 // stacked weight row (0..16383)
    const int gate = n >> 12;
    const int nl = n & (HID - 1);
    const float* src = (gate == 0) ? Wf : (gate == 1) ? Wi : (gate == 2) ? Wc : Wo;
    const float* row = src + (size_t)nl * KX;
    __nv_bfloat16* hi = g_whi + (size_t)n * KX;
    __nv_bfloat16* lo = g_wlo + (size_t)n * KX;
    for (int k4 = threadIdx.x; k4 < KX / 4; k4 += blockDim.x) {
        int k = k4 * 4;
        split4_store(*(const float4*)(row + k), &hi[k], &lo[k]);
    }
}

__global__ void convert_wout_kernel(const float* __restrict__ W) {
    const int n = blockIdx.x;
    const float* row = W + (size_t)n * HID;
    __nv_bfloat16* hi = g_wouthi + (size_t)n * HID;
    __nv_bfloat16* lo = g_woutlo + (size_t)n * HID;
    for (int k4 = threadIdx.x; k4 < HID / 4; k4 += blockDim.x) {
        int k = k4 * 4;
        split4_store(*(const float4*)(row + k), &hi[k], &lo[k]);
    }
}

// ---------------- wmma split-bf16 GEMM: C[M,N] = A[M,K] @ W[N,K]^T ----------------
// C = Ahi*Whi + Ahi*Wlo + Alo*Whi  (fp32 accum, wmma 16x16x16 bf16).
// CTA tile 128M x 256N, k-step 32, 512 threads = 16 warps (4M x 4N, 32x64 each).
// 3-stage cp.async pipeline, loads 2 iters ahead, ONE barrier per iter.
#define WLD    40                       // smem leading dim (elements); 80 B rows
#define A_EL   (128 * WLD)              // A matrix buffer elements (hi or lo)
#define W_EL   (256 * WLD)              // W matrix buffer elements (hi or lo)
#define STEL   (2 * A_EL + 2 * W_EL)    // per stage: [Ah][Al][Wh][Wl] = 30720 el

template <int PASS_ID>
__global__ __launch_bounds__(512, 1)
void gemm_wmma_kernel()
{
    constexpr int N = (PASS_ID == 0) ? G4 : OUT_DIM;
    constexpr int K = (PASS_ID == 0) ? KX : HID;
    const __nv_bfloat16* __restrict__ Ahi = (PASS_ID == 0) ? g_xhi : g_hthi;
    const __nv_bfloat16* __restrict__ Alo = (PASS_ID == 0) ? g_xlo : g_htlo;
    const __nv_bfloat16* __restrict__ Whi = (PASS_ID == 0) ? g_whi : g_wouthi;
    const __nv_bfloat16* __restrict__ Wlo = (PASS_ID == 0) ? g_wlo : g_woutlo;
    float* __restrict__ C = (PASS_ID == 0) ? g_gates : g_logits;

    extern __shared__ __align__(16) __nv_bfloat16 smem[];   // 3 * STEL elements
    const uint32_t sbase = smem_u32(smem);

    const int tid  = threadIdx.x;
    const int wid  = tid >> 5;
    const int warp_m = wid & 3;    // 4 warps over M, 32 rows each
    const int warp_n = wid >> 2;   // 4 warps over N, 64 cols each

    const int m0 = blockIdx.x * 128;
    const int n0 = blockIdx.y * 256;
    const int niter = K / 32;

    // producer mapping: A has 512 16B-chunks per matrix (1/thread);
    // W has 1024 (2/thread: tid, tid+512). chunk ch -> row ch>>2, 16B col ch&3.
    const int rA = tid >> 2, cA = tid & 3;     // A row 0..127, W rows rA and rA+128

    const __nv_bfloat16* pAh = Ahi + (size_t)(m0 + rA) * K + cA * 8;
    const __nv_bfloat16* pAl = Alo + (size_t)(m0 + rA) * K + cA * 8;
    const __nv_bfloat16* pWh0 = Whi + (size_t)(n0 + rA) * K + cA * 8;
    const __nv_bfloat16* pWh1 = Whi + (size_t)(n0 + rA + 128) * K + cA * 8;
    const __nv_bfloat16* pWl0 = Wlo + (size_t)(n0 + rA) * K + cA * 8;
    const __nv_bfloat16* pWl1 = Wlo + (size_t)(n0 + rA + 128) * K + cA * 8;

    const uint32_t sA  = (uint32_t)(rA * WLD + cA * 8) * 2;            // byte offsets
    const uint32_t sW0 = sA;                                            // within W buf
    const uint32_t sW1 = (uint32_t)((rA + 128) * WLD + cA * 8) * 2;

    auto issue_stage = [&](int stage, int it) {
        const uint32_t st = sbase + (uint32_t)(stage * STEL) * 2;
        const int k0 = it * 32;
        cp16(st + sA,                                pAh + k0);
        cp16(st + A_EL * 2 + sA,                     pAl + k0);
        cp16(st + 2 * A_EL * 2 + sW0,                pWh0 + k0);
        cp16(st + 2 * A_EL * 2 + sW1,                pWh1 + k0);
        cp16(st + (2 * A_EL + W_EL) * 2 + sW0,       pWl0 + k0);
        cp16(st + (2 * A_EL + W_EL) * 2 + sW1,       pWl1 + k0);
    };

    wmma::fragment<wmma::accumulator, 16, 16, 16, float> acc[2][4];
#pragma unroll
    for (int i = 0; i < 2; i++)
#pragma unroll
        for (int j = 0; j < 4; j++) wmma::fill_fragment(acc[i][j], 0.0f);

    // prologue: stages 0 and 1 in flight
    issue_stage(0, 0); cp_commit();
    issue_stage(1, 1); cp_commit();

    int stage = 0;
    for (int it = 0; it < niter; ++it) {
        cp_wait1();        // group for `it` done (group it+1 may be pending)
        __syncthreads();   // all warps see stage data; stage (it+2)%3 has no readers

        if (it + 2 < niter) issue_stage((stage + 2) % 3, it + 2);
        cp_commit();       // exactly one group per iteration (may be empty)

        const __nv_bfloat16* sAh = smem + stage * STEL;
        const __nv_bfloat16* sAl = sAh + A_EL;
        const __nv_bfloat16* sWh = sAh + 2 * A_EL;
        const __nv_bfloat16* sWl = sAh + 2 * A_EL + W_EL;

#pragma unroll
        for (int kk = 0; kk < 32; kk += 16) {
            wmma::fragment<wmma::matrix_a, 16, 16, 16, __nv_bfloat16, wmma::row_major> fah[2], fal[2];
#pragma unroll
            for (int i = 0; i < 2; i++) {
                wmma::load_matrix_sync(fah[i], &sAh[(warp_m * 32 + i * 16) * WLD + kk], WLD);
                wmma::load_matrix_sync(fal[i], &sAl[(warp_m * 32 + i * 16) * WLD + kk], WLD);
            }
#pragma unroll
            for (int j4 = 0; j4 < 2; ++j4) {   // two halves of 4 n-frags (reg liveness)
                wmma::fragment<wmma::matrix_b, 16, 16, 16, __nv_bfloat16, wmma::col_major> fbh[2], fbl[2];
#pragma unroll
                for (int j = 0; j < 2; j++) {
                    const int nf = warp_n * 64 + (j4 * 2 + j) * 16;
                    wmma::load_matrix_sync(fbh[j], &sWh[nf * WLD + kk], WLD);
                    wmma::load_matrix_sync(fbl[j], &sWl[nf * WLD + kk], WLD);
                }
#pragma unroll
                for (int j = 0; j < 2; j++)
#pragma unroll
                    for (int i = 0; i < 2; i++)
                        wmma::mma_sync(acc[i][j4 * 2 + j], fah[i], fbh[j], acc[i][j4 * 2 + j]);
#pragma unroll
                for (int j = 0; j < 2; j++)
#pragma unroll
                    for (int i = 0; i < 2; i++)
                        wmma::mma_sync(acc[i][j4 * 2 + j], fah[i], fbl[j], acc[i][j4 * 2 + j]);
#pragma unroll
                for (int j = 0; j < 2; j++)
#pragma unroll
                    for (int i = 0; i < 2; i++)
                        wmma::mma_sync(acc[i][j4 * 2 + j], fal[i], fbh[j], acc[i][j4 * 2 + j]);
            }
        }
        stage = (stage + 1) % 3;
    }

#pragma unroll
    for (int i = 0; i < 2; i++)
#pragma unroll
        for (int j = 0; j < 4; j++) {
            float* p = C + (size_t)(m0 + warp_m * 32 + i * 16) * N + n0 + warp_n * 64 + j * 16;
            wmma::store_matrix_sync(p, acc[i][j], N, wmma::mem_row_major);
        }
}

// ---------------- LSTM elementwise ----------------
__global__ void lstm_act_kernel(const float* __restrict__ cin,
                                const float* __restrict__ bf, const float* __restrict__ bi,
                                const float* __restrict__ bc, const float* __restrict__ bo,
                                float* __restrict__ out_it, float* __restrict__ out_ht,
                                float* __restrict__ out_ct)
{
    int idx = blockIdx.x * blockDim.x + threadIdx.x;
    if (idx >= BATCH * HID) return;
    int b = idx / HID;
    int j = idx - b * HID;
    const float* g = g_gates + (size_t)b * G4;
    float fp = g[j]           + bf[j];
    float ip = g[HID + j]     + bi[j];
    float cp = g[2 * HID + j] + bc[j];
    float op = g[3 * HID + j] + bo[j];
    float ft = 1.f / (1.f + __expf(-fp));
    float it = 1.f / (1.f + __expf(-ip));
    float cb = tanhf(cp);
    float ct = ft * cin[idx] + it * cb;
    float ot = 1.f / (1.f + __expf(-op));
    float ht = ot * tanhf(ct);
    out_it[idx] = it;
    out_ht[idx] = ht;
    out_ct[idx] = ct;
    __nv_bfloat16 hh = __float2bfloat16(ht);
    g_hthi[idx] = hh;
    g_htlo[idx] = __float2bfloat16(ht - __bfloat162float(hh));
}

// ---------------- log_softmax ----------------
__global__ void logsoftmax_kernel(const float* __restrict__ bout,
                                  float* __restrict__ out)
{
    const int row = blockIdx.x;
    const float* x = g_logits + (size_t)row * OUT_DIM;
    float* y = out + (size_t)row * OUT_DIM;
    __shared__ float red[256];
    const int tid = threadIdx.x;

    float mx = -INFINITY;
    for (int j = tid; j < OUT_DIM; j += 256) mx = fmaxf(mx, x[j] + bout[j]);
    red[tid] = mx; __syncthreads();
    for (int s = 128; s > 0; s >>= 1) {
        if (tid < s) red[tid] = fmaxf(red[tid], red[tid + s]);
        __syncthreads();
    }
    mx = red[0];
    __syncthreads();

    float sum = 0.f;
    for (int j = tid; j < OUT_DIM; j += 256) sum += __expf(x[j] + bout[j] - mx);
    red[tid] = sum; __syncthreads();
    for (int s = 128; s > 0; s >>= 1) {
        if (tid < s) red[tid] += red[tid + s];
        __syncthreads();
    }
    float lse = mx + logf(red[0]);

    for (int j = tid; j < OUT_DIM; j += 256) y[j] = x[j] + bout[j] - lse;
}

// ---------------- launch ----------------
extern "C" void kernel_launch(void* const* d_in, const int* in_sizes, int n_in,
                              void* d_out, int out_size)
{
    const float* in_i  = (const float*)d_in[0];
    const float* in_h  = (const float*)d_in[1];
    const float* in_c  = (const float*)d_in[2];
    const float* Wf    = (const float*)d_in[3];
    const float* bf_   = (const float*)d_in[4];
    const float* Wi    = (const float*)d_in[5];
    const float* bi_   = (const float*)d_in[6];
    const float* Wc    = (const float*)d_in[7];
    const float* bc_   = (const float*)d_in[8];
    const float* Wo    = (const float*)d_in[9];
    const float* bo_   = (const float*)d_in[10];
    const float* Wout  = (const float*)d_in[11];
    const float* bout  = (const float*)d_in[12];

    float* out    = (float*)d_out;
    float* out_it = out;
    float* out_ht = out + (size_t)BATCH * HID;
    float* out_ct = out + 2 * (size_t)BATCH * HID;
    float* out_ls = out + 3 * (size_t)BATCH * HID;

    const int SMEM_DYN = 3 * STEL * 2;   // 3 stages * 61440 B = 184320
    cudaFuncSetAttribute(gemm_wmma_kernel<0>,
                         cudaFuncAttributeMaxDynamicSharedMemorySize, SMEM_DYN);
    cudaFuncSetAttribute(gemm_wmma_kernel<1>,
                         cudaFuncAttributeMaxDynamicSharedMemorySize, SMEM_DYN);

    // 1) fp32 -> bf16 hi/lo conversions (vectorized)
    convert_x_kernel<<<BATCH, 256>>>(in_i, in_h);
    convert_w_kernel<<<G4, 256>>>(Wf, Wi, Wc, Wo);
    convert_wout_kernel<<<OUT_DIM, 256>>>(Wout);

    // 2) gates = x @ [Wf;Wi;Wc;Wo]^T
    {
        dim3 grid(BATCH / 128, G4 / 256);
        gemm_wmma_kernel<0><<<grid, 512, SMEM_DYN>>>();
    }

    // 3) elementwise LSTM cell -> it, ht, ct (+ ht split)
    {
        int total = BATCH * HID;
        lstm_act_kernel<<<(total + 255) / 256, 256>>>(in_c, bf_, bi_, bc_, bo_,
                                                      out_it, out_ht, out_ct);
    }

    // 4) logits = ht @ Wout^T
    {
        dim3 grid(BATCH / 128, OUT_DIM / 256);
        gemm_wmma_kernel<1><<<grid, 512, SMEM_DYN>>>();
    }

    // 5) log_softmax(logits + bout) -> out
    logsoftmax_kernel<<<BATCH, 256>>>(bout, out_ls);
}

// round 12
// speedup vs baseline: 2.5122x; 1.1295x over previous
#include <cuda_runtime.h>
#include <cuda_bf16.h>
#include <math.h>
#include <stdint.h>

// Problem dims (fixed per reference)
#define BATCH   1024
#define IN_DIM  1024
#define HID     4096
#define KX      (IN_DIM + HID)   // 5120
#define G4      (4 * HID)        // 16384
#define OUT_DIM 4096

// ---------------- scratch (no cudaMalloc allowed) ----------------
// Referenced ONLY inside device code (host-side use would get the host shadow).
__device__ __align__(16) __nv_bfloat16 g_xhi[BATCH * KX];
__device__ __align__(16) __nv_bfloat16 g_xlo[BATCH * KX];
__device__ __align__(16) __nv_bfloat16 g_whi[(size_t)G4 * KX];
__device__ __align__(16) __nv_bfloat16 g_wlo[(size_t)G4 * KX];
__device__ __align__(16) __nv_bfloat16 g_wouthi[(size_t)OUT_DIM * HID];
__device__ __align__(16) __nv_bfloat16 g_woutlo[(size_t)OUT_DIM * HID];
__device__ __align__(16) __nv_bfloat16 g_hthi[BATCH * HID];
__device__ __align__(16) __nv_bfloat16 g_htlo[BATCH * HID];
__device__ float g_gates[(size_t)BATCH * G4];
__device__ float g_logits[(size_t)BATCH * OUT_DIM];

// ---------------- PTX helpers ----------------
__device__ __forceinline__ uint32_t smem_u32(const void* p) {
    uint32_t a;
    asm("{ .reg .u64 t; cvta.to.shared.u64 t, %1; cvt.u32.u64 %0, t; }" : "=r"(a) : "l"(p));
    return a;
}
__device__ __forceinline__ void cp16(uint32_t s, const void* g) {
    asm volatile("cp.async.cg.shared.global [%0], [%1], 16;" :: "r"(s), "l"(g) : "memory");
}
__device__ __forceinline__ void cp_commit() {
    asm volatile("cp.async.commit_group;" ::: "memory");
}
__device__ __forceinline__ void cp_wait1() {
    asm volatile("cp.async.wait_group 1;" ::: "memory");
}
__device__ __forceinline__ void ldsm4(uint32_t* r, uint32_t addr) {
    asm volatile("ldmatrix.sync.aligned.m8n8.x4.shared.b16 {%0,%1,%2,%3}, [%4];"
                 : "=r"(r[0]), "=r"(r[1]), "=r"(r[2]), "=r"(r[3]) : "r"(addr));
}
__device__ __forceinline__ void mma16816(float* d, const uint32_t* a, uint32_t b0, uint32_t b1) {
    asm volatile("mma.sync.aligned.m16n8k16.row.col.f32.bf16.bf16.f32 "
                 "{%0,%1,%2,%3}, {%4,%5,%6,%7}, {%8,%9}, {%0,%1,%2,%3};"
                 : "+f"(d[0]), "+f"(d[1]), "+f"(d[2]), "+f"(d[3])
                 : "r"(a[0]), "r"(a[1]), "r"(a[2]), "r"(a[3]), "r"(b0), "r"(b1));
}

// ---------------- fp32 -> bf16 hi/lo conversion (vectorized) ----------------
__device__ __forceinline__ void split4_store(float4 v, __nv_bfloat16* hi, __nv_bfloat16* lo) {
    float vv[4] = {v.x, v.y, v.z, v.w};
    uint32_t hw[2], lw[2];
#pragma unroll
    for (int p = 0; p < 2; p++) {
        __nv_bfloat16 h0 = __float2bfloat16(vv[2 * p]);
        __nv_bfloat16 h1 = __float2bfloat16(vv[2 * p + 1]);
        __nv_bfloat16 l0 = __float2bfloat16(vv[2 * p]     - __bfloat162float(h0));
        __nv_bfloat16 l1 = __float2bfloat16(vv[2 * p + 1] - __bfloat162float(h1));
        hw[p] = (uint32_t)__bfloat16_as_ushort(h0) | ((uint32_t)__bfloat16_as_ushort(h1) << 16);
        lw[p] = (uint32_t)__bfloat16_as_ushort(l0) | ((uint32_t)__bfloat16_as_ushort(l1) << 16);
    }
    *(uint2*)hi = make_uint2(hw[0], hw[1]);
    *(uint2*)lo = make_uint2(lw[0], lw[1]);
}

__global__ void convert_x_kernel(const float* __restrict__ i_, const float* __restrict__ h_) {
    const int b = blockIdx.x;
    for (int k4 = threadIdx.x; k4 < KX / 4; k4 += blockDim.x) {
        int k = k4 * 4;
        float4 v = (k < IN_DIM) ? *(const float4*)(i_ + (size_t)b * IN_DIM + k)
                                : *(const float4*)(h_ + (size_t)b * HID + (k - IN_DIM));
        split4_store(v, &g_xhi[(size_t)b * KX + k], &g_xlo[(size_t)b * KX + k]);
    }
}

__global__ void convert_w_kernel(const float* __restrict__ Wf, const float* __restrict__ Wi,
                                 const float* __restrict__ Wc, const float* __restrict__ Wo) {
    const int n = blockIdx.x;                 // stacked weight row (0..16383)
    const int gate = n >> 12;
    const int nl = n & (HID - 1);
    const float* src = (gate == 0) ? Wf : (gate == 1) ? Wi : (gate == 2) ? Wc : Wo;
    const float* row = src + (size_t)nl * KX;
    __nv_bfloat16* hi = g_whi + (size_t)n * KX;
    __nv_bfloat16* lo = g_wlo + (size_t)n * KX;
    for (int k4 = threadIdx.x; k4 < KX / 4; k4 += blockDim.x) {
        int k = k4 * 4;
        split4_store(*(const float4*)(row + k), &hi[k], &lo[k]);
    }
}

__global__ void convert_wout_kernel(const float* __restrict__ W) {
    const int n = blockIdx.x;
    const float* row = W + (size_t)n * HID;
    __nv_bfloat16* hi = g_wouthi + (size_t)n * HID;
    __nv_bfloat16* lo = g_woutlo + (size_t)n * HID;
    for (int k4 = threadIdx.x; k4 < HID / 4; k4 += blockDim.x) {
        int k = k4 * 4;
        split4_store(*(const float4*)(row + k), &hi[k], &lo[k]);
    }
}

// ---------------- raw-mma split-bf16 GEMM: C[M,N] = A[M,K] @ W[N,K]^T ----------------
// C = Ahi*Whi + Ahi*Wlo + Alo*Whi  (fp32 accum, mma.sync m16n8k16).
// CTA 128M x 256N, k-step 32, 256 threads = 8 warps, 64x64 per warp (2M x 4N warps).
// 3-stage cp.async pipeline, loads 2 iters ahead, ONE barrier per iter.
// Padded smem rows (80 B): ldmatrix 16B-row pattern is provably conflict-free.
#define WLD    40                       // smem leading dim (elements); 80 B rows
#define A_EL   (128 * WLD)              // A matrix buffer elements (hi or lo)
#define W_EL   (256 * WLD)              // W matrix buffer elements (hi or lo)
#define STEL   (2 * A_EL + 2 * W_EL)    // per stage: [Ah][Al][Wh][Wl] = 30720 el

template <int PASS_ID>
__global__ __launch_bounds__(256, 1)
void gemm_mma_kernel()
{
    constexpr int N = (PASS_ID == 0) ? G4 : OUT_DIM;
    constexpr int K = (PASS_ID == 0) ? KX : HID;
    const __nv_bfloat16* __restrict__ Ahi = (PASS_ID == 0) ? g_xhi : g_hthi;
    const __nv_bfloat16* __restrict__ Alo = (PASS_ID == 0) ? g_xlo : g_htlo;
    const __nv_bfloat16* __restrict__ Whi = (PASS_ID == 0) ? g_whi : g_wouthi;
    const __nv_bfloat16* __restrict__ Wlo = (PASS_ID == 0) ? g_wlo : g_woutlo;
    float* __restrict__ C = (PASS_ID == 0) ? g_gates : g_logits;

    extern __shared__ __align__(16) __nv_bfloat16 smem[];   // 3 * STEL elements
    const uint32_t sbase = smem_u32(smem);

    const int tid  = threadIdx.x;
    const int lane = tid & 31;
    const int wid  = tid >> 5;
    const int warp_m = wid & 1;    // 2 warps over M, 64 rows each
    const int warp_n = wid >> 1;   // 4 warps over N, 64 cols each

    const int m0 = blockIdx.x * 128;
    const int n0 = blockIdx.y * 256;
    const int niter = K / 32;

    // ---- producer mapping: 16B chunks; A 512/matrix (2/thr), W 1024/matrix (4/thr)
    const int rP = tid >> 2, cP = tid & 3;
    const __nv_bfloat16* pA[2][2];   // [hi/lo][part]
    const __nv_bfloat16* pW[2][4];
    uint32_t sOffA[2], sOffW[4];
#pragma unroll
    for (int p = 0; p < 2; p++) {
        const int r = rP + 64 * p;
        pA[0][p] = Ahi + (size_t)(m0 + r) * K + cP * 8;
        pA[1][p] = Alo + (size_t)(m0 + r) * K + cP * 8;
        sOffA[p] = (uint32_t)(r * WLD + cP * 8) * 2;
    }
#pragma unroll
    for (int p = 0; p < 4; p++) {
        const int r = rP + 64 * p;
        pW[0][p] = Whi + (size_t)(n0 + r) * K + cP * 8;
        pW[1][p] = Wlo + (size_t)(n0 + r) * K + cP * 8;
        sOffW[p] = (uint32_t)(r * WLD + cP * 8) * 2;
    }

    auto issue_stage = [&](int stage, int it) {
        const uint32_t st = sbase + (uint32_t)(stage * STEL) * 2;
        const int k0 = it * 32;
#pragma unroll
        for (int p = 0; p < 2; p++) {
            cp16(st + sOffA[p],            pA[0][p] + k0);
            cp16(st + A_EL * 2 + sOffA[p], pA[1][p] + k0);
        }
#pragma unroll
        for (int p = 0; p < 4; p++) {
            cp16(st + 2 * A_EL * 2 + sOffW[p],           pW[0][p] + k0);
            cp16(st + (2 * A_EL + W_EL) * 2 + sOffW[p],  pW[1][p] + k0);
        }
    };

    // ---- consumer ldmatrix lane addressing (byte offsets within a matrix buffer)
    // A x4 (m16 x k16): groups g0 rows i@kk, g1 rows 8+i@kk, g2 rows i@kk+8, g3 rows 8+i@kk+8
    const uint32_t aLane = (uint32_t)(((warp_m * 64) + (lane & 7) + ((lane >> 3) & 1) * 8) * WLD
                                      + (lane >> 4) * 8) * 2;
    // B x4 (two n8 x k16 frags): g0 n+i@kk, g1 n+i@kk+8, g2 n+8+i@kk, g3 n+8+i@kk+8
    const uint32_t bLane = (uint32_t)(((warp_n * 64) + (lane & 7) + (lane >> 4) * 8) * WLD
                                      + ((lane >> 3) & 1) * 8) * 2;

    float acc[4][8][4];
#pragma unroll
    for (int mt = 0; mt < 4; mt++)
#pragma unroll
        for (int j = 0; j < 8; j++)
#pragma unroll
            for (int r = 0; r < 4; r++) acc[mt][j][r] = 0.f;

    // prologue: stages 0 and 1 in flight
    issue_stage(0, 0); cp_commit();
    issue_stage(1, 1); cp_commit();

    int stage = 0;
    for (int it = 0; it < niter; ++it) {
        cp_wait1();        // group for `it` done (group it+1 may be pending)
        __syncthreads();   // all warps see stage data; stage (it+2)%3 has no readers

        if (it + 2 < niter) issue_stage((stage + 2) % 3, it + 2);
        cp_commit();       // exactly one group per iteration (may be empty)

        const uint32_t sAh = sbase + (uint32_t)(stage * STEL) * 2;
        const uint32_t sAl = sAh + A_EL * 2;
        const uint32_t sWh = sAh + 2 * A_EL * 2;
        const uint32_t sWl = sAh + (2 * A_EL + W_EL) * 2;

#pragma unroll
        for (int kk = 0; kk < 2; ++kk) {
            const uint32_t kb = kk * 32;   // 16 elements = 32 bytes

            uint32_t ah[4][4], al[4][4], bhf[16], blf[16];
#pragma unroll
            for (int mt = 0; mt < 4; ++mt) {
                const uint32_t ra = (uint32_t)(mt * 16 * WLD) * 2 + aLane + kb;
                ldsm4(ah[mt], sAh + ra);
                ldsm4(al[mt], sAl + ra);
            }
#pragma unroll
            for (int np = 0; np < 4; ++np) {
                const uint32_t rb = (uint32_t)(np * 16 * WLD) * 2 + bLane + kb;
                ldsm4(&bhf[4 * np], sWh + rb);
                ldsm4(&blf[4 * np], sWl + rb);
            }
            // term-outermost: acc reuse distance 32 MMAs
#pragma unroll
            for (int mt = 0; mt < 4; ++mt)
#pragma unroll
                for (int j = 0; j < 8; ++j)
                    mma16816(acc[mt][j], ah[mt], bhf[2 * j], bhf[2 * j + 1]);
#pragma unroll
            for (int mt = 0; mt < 4; ++mt)
#pragma unroll
                for (int j = 0; j < 8; ++j)
                    mma16816(acc[mt][j], ah[mt], blf[2 * j], blf[2 * j + 1]);
#pragma unroll
            for (int mt = 0; mt < 4; ++mt)
#pragma unroll
                for (int j = 0; j < 8; ++j)
                    mma16816(acc[mt][j], al[mt], bhf[2 * j], bhf[2 * j + 1]);
        }
        stage = (stage + 1) % 3;
    }

    // ---- epilogue: m16n8 frag -> d0,d1 @(row,col), d2,d3 @(row+8,col)
    const int erow = lane >> 2;
    const int ecol = (lane & 3) * 2;
    float* Cw = C + (size_t)(m0 + warp_m * 64) * N + n0 + warp_n * 64;
#pragma unroll
    for (int mt = 0; mt < 4; ++mt)
#pragma unroll
        for (int j = 0; j < 8; ++j) {
            float* p0 = Cw + (size_t)(mt * 16 + erow) * N + j * 8 + ecol;
            *(float2*)p0                   = make_float2(acc[mt][j][0], acc[mt][j][1]);
            *(float2*)(p0 + (size_t)8 * N) = make_float2(acc[mt][j][2], acc[mt][j][3]);
        }
}

// ---------------- LSTM elementwise ----------------
__global__ void lstm_act_kernel(const float* __restrict__ cin,
                                const float* __restrict__ bf, const float* __restrict__ bi,
                                const float* __restrict__ bc, const float* __restrict__ bo,
                                float* __restrict__ out_it, float* __restrict__ out_ht,
                                float* __restrict__ out_ct)
{
    int idx = blockIdx.x * blockDim.x + threadIdx.x;
    if (idx >= BATCH * HID) return;
    int b = idx / HID;
    int j = idx - b * HID;
    const float* g = g_gates + (size_t)b * G4;
    float fp = g[j]           + bf[j];
    float ip = g[HID + j]     + bi[j];
    float cp = g[2 * HID + j] + bc[j];
    float op = g[3 * HID + j] + bo[j];
    float ft = 1.f / (1.f + __expf(-fp));
    float it = 1.f / (1.f + __expf(-ip));
    float cb = tanhf(cp);
    float ct = ft * cin[idx] + it * cb;
    float ot = 1.f / (1.f + __expf(-op));
    float ht = ot * tanhf(ct);
    out_it[idx] = it;
    out_ht[idx] = ht;
    out_ct[idx] = ct;
    __nv_bfloat16 hh = __float2bfloat16(ht);
    g_hthi[idx] = hh;
    g_htlo[idx] = __float2bfloat16(ht - __bfloat162float(hh));
}

// ---------------- log_softmax ----------------
__global__ void logsoftmax_kernel(const float* __restrict__ bout,
                                  float* __restrict__ out)
{
    const int row = blockIdx.x;
    const float* x = g_logits + (size_t)row * OUT_DIM;
    float* y = out + (size_t)row * OUT_DIM;
    __shared__ float red[256];
    const int tid = threadIdx.x;

    float mx = -INFINITY;
    for (int j = tid; j < OUT_DIM; j += 256) mx = fmaxf(mx, x[j] + bout[j]);
    red[tid] = mx; __syncthreads();
    for (int s = 128; s > 0; s >>= 1) {
        if (tid < s) red[tid] = fmaxf(red[tid], red[tid + s]);
        __syncthreads();
    }
    mx = red[0];
    __syncthreads();

    float sum = 0.f;
    for (int j = tid; j < OUT_DIM; j += 256) sum += __expf(x[j] + bout[j] - mx);
    red[tid] = sum; __syncthreads();
    for (int s = 128; s > 0; s >>= 1) {
        if (tid < s) red[tid] += red[tid + s];
        __syncthreads();
    }
    float lse = mx + logf(red[0]);

    for (int j = tid; j < OUT_DIM; j += 256) y[j] = x[j] + bout[j] - lse;
}

// ---------------- launch ----------------
extern "C" void kernel_launch(void* const* d_in, const int* in_sizes, int n_in,
                              void* d_out, int out_size)
{
    const float* in_i  = (const float*)d_in[0];
    const float* in_h  = (const float*)d_in[1];
    const float* in_c  = (const float*)d_in[2];
    const float* Wf    = (const float*)d_in[3];
    const float* bf_   = (const float*)d_in[4];
    const float* Wi    = (const float*)d_in[5];
    const float* bi_   = (const float*)d_in[6];
    const float* Wc    = (const float*)d_in[7];
    const float* bc_   = (const float*)d_in[8];
    const float* Wo    = (const float*)d_in[9];
    const float* bo_   = (const float*)d_in[10];
    const float* Wout  = (const float*)d_in[11];
    const float* bout  = (const float*)d_in[12];

    float* out    = (float*)d_out;
    float* out_it = out;
    float* out_ht = out + (size_t)BATCH * HID;
    float* out_ct = out + 2 * (size_t)BATCH * HID;
    float* out_ls = out + 3 * (size_t)BATCH * HID;

    const int SMEM_DYN = 3 * STEL * 2;   // 3 stages * 61440 B = 184320
    cudaFuncSetAttribute(gemm_mma_kernel<0>,
                         cudaFuncAttributeMaxDynamicSharedMemorySize, SMEM_DYN);
    cudaFuncSetAttribute(gemm_mma_kernel<1>,
                         cudaFuncAttributeMaxDynamicSharedMemorySize, SMEM_DYN);

    // 1) fp32 -> bf16 hi/lo conversions (vectorized)
    convert_x_kernel<<<BATCH, 256>>>(in_i, in_h);
    convert_w_kernel<<<G4, 256>>>(Wf, Wi, Wc, Wo);
    convert_wout_kernel<<<OUT_DIM, 256>>>(Wout);

    // 2) gates = x @ [Wf;Wi;Wc;Wo]^T
    {
        dim3 grid(BATCH / 128, G4 / 256);
        gemm_mma_kernel<0><<<grid, 256, SMEM_DYN>>>();
    }

    // 3) elementwise LSTM cell -> it, ht, ct (+ ht split)
    {
        int total = BATCH * HID;
        lstm_act_kernel<<<(total + 255) / 256, 256>>>(in_c, bf_, bi_, bc_, bo_,
                                                      out_it, out_ht, out_ct);
    }

    // 4) logits = ht @ Wout^T
    {
        dim3 grid(BATCH / 128, OUT_DIM / 256);
        gemm_mma_kernel<1><<<grid, 256, SMEM_DYN>>>();
    }

    // 5) log_softmax(logits + bout) -> out
    logsoftmax_kernel<<<BATCH, 256>>>(bout, out_ls);
}

// round 13
// speedup vs baseline: 2.9080x; 1.1576x over previous
#include <cuda_runtime.h>
#include <cuda_bf16.h>
#include <math.h>
#include <stdint.h>

// Problem dims (fixed per reference)
#define BATCH   1024
#define IN_DIM  1024
#define HID     4096
#define KX      (IN_DIM + HID)   // 5120
#define G4      (4 * HID)        // 16384
#define OUT_DIM 4096

// ---------------- scratch (no cudaMalloc allowed) ----------------
// Referenced ONLY inside device code (host-side use would get the host shadow).
__device__ __align__(16) __nv_bfloat16 g_xhi[BATCH * KX];
__device__ __align__(16) __nv_bfloat16 g_xlo[BATCH * KX];
__device__ __align__(16) __nv_bfloat16 g_whi[(size_t)G4 * KX];
__device__ __align__(16) __nv_bfloat16 g_wlo[(size_t)G4 * KX];
__device__ __align__(16) __nv_bfloat16 g_wouthi[(size_t)OUT_DIM * HID];
__device__ __align__(16) __nv_bfloat16 g_woutlo[(size_t)OUT_DIM * HID];
__device__ __align__(16) __nv_bfloat16 g_hthi[BATCH * HID];
__device__ __align__(16) __nv_bfloat16 g_htlo[BATCH * HID];
__device__ float g_gates[(size_t)BATCH * G4];
__device__ float g_logits[(size_t)BATCH * OUT_DIM];

// ---------------- PTX helpers ----------------
__device__ __forceinline__ uint32_t smem_u32(const void* p) {
    uint32_t a;
    asm("{ .reg .u64 t; cvta.to.shared.u64 t, %1; cvt.u32.u64 %0, t; }" : "=r"(a) : "l"(p));
    return a;
}
__device__ __forceinline__ void cp16(uint32_t s, const void* g) {
    asm volatile("cp.async.cg.shared.global [%0], [%1], 16;" :: "r"(s), "l"(g) : "memory");
}
__device__ __forceinline__ void cp_commit() {
    asm volatile("cp.async.commit_group;" ::: "memory");
}
__device__ __forceinline__ void cp_wait0() {
    asm volatile("cp.async.wait_group 0;" ::: "memory");
}
__device__ __forceinline__ void ldsm4(uint32_t* r, uint32_t addr) {
    asm volatile("ldmatrix.sync.aligned.m8n8.x4.shared.b16 {%0,%1,%2,%3}, [%4];"
                 : "=r"(r[0]), "=r"(r[1]), "=r"(r[2]), "=r"(r[3]) : "r"(addr));
}
__device__ __forceinline__ void mma16816(float* d, const uint32_t* a, uint32_t b0, uint32_t b1) {
    asm volatile("mma.sync.aligned.m16n8k16.row.col.f32.bf16.bf16.f32 "
                 "{%0,%1,%2,%3}, {%4,%5,%6,%7}, {%8,%9}, {%0,%1,%2,%3};"
                 : "+f"(d[0]), "+f"(d[1]), "+f"(d[2]), "+f"(d[3])
                 : "r"(a[0]), "r"(a[1]), "r"(a[2]), "r"(a[3]), "r"(b0), "r"(b1));
}

// ---------------- fp32 -> bf16 hi/lo conversion (vectorized) ----------------
__device__ __forceinline__ void split4_store(float4 v, __nv_bfloat16* hi, __nv_bfloat16* lo) {
    float vv[4] = {v.x, v.y, v.z, v.w};
    uint32_t hw[2], lw[2];
#pragma unroll
    for (int p = 0; p < 2; p++) {
        __nv_bfloat16 h0 = __float2bfloat16(vv[2 * p]);
        __nv_bfloat16 h1 = __float2bfloat16(vv[2 * p + 1]);
        __nv_bfloat16 l0 = __float2bfloat16(vv[2 * p]     - __bfloat162float(h0));
        __nv_bfloat16 l1 = __float2bfloat16(vv[2 * p + 1] - __bfloat162float(h1));
        hw[p] = (uint32_t)__bfloat16_as_ushort(h0) | ((uint32_t)__bfloat16_as_ushort(h1) << 16);
        lw[p] = (uint32_t)__bfloat16_as_ushort(l0) | ((uint32_t)__bfloat16_as_ushort(l1) << 16);
    }
    *(uint2*)hi = make_uint2(hw[0], hw[1]);
    *(uint2*)lo = make_uint2(lw[0], lw[1]);
}

__global__ void convert_x_kernel(const float* __restrict__ i_, const float* __restrict__ h_) {
    const int b = blockIdx.x;
    for (int k4 = threadIdx.x; k4 < KX / 4; k4 += blockDim.x) {
        int k = k4 * 4;
        float4 v = (k < IN_DIM) ? *(const float4*)(i_ + (size_t)b * IN_DIM + k)
                                : *(const float4*)(h_ + (size_t)b * HID + (k - IN_DIM));
        split4_store(v, &g_xhi[(size_t)b * KX + k], &g_xlo[(size_t)b * KX + k]);
    }
}

__global__ void convert_w_kernel(const float* __restrict__ Wf, const float* __restrict__ Wi,
                                 const float* __restrict__ Wc, const float* __restrict__ Wo) {
    const int n = blockIdx.x;                 // stacked weight row (0..16383)
    const int gate = n >> 12;
    const int nl = n & (HID - 1);
    const float* src = (gate == 0) ? Wf : (gate == 1) ? Wi : (gate == 2) ? Wc : Wo;
    const float* row = src + (size_t)nl * KX;
    __nv_bfloat16* hi = g_whi + (size_t)n * KX;
    __nv_bfloat16* lo = g_wlo + (size_t)n * KX;
    for (int k4 = threadIdx.x; k4 < KX / 4; k4 += blockDim.x) {
        int k = k4 * 4;
        split4_store(*(const float4*)(row + k), &hi[k], &lo[k]);
    }
}

__global__ void convert_wout_kernel(const float* __restrict__ W) {
    const int n = blockIdx.x;
    const float* row = W + (size_t)n * HID;
    __nv_bfloat16* hi = g_wouthi + (size_t)n * HID;
    __nv_bfloat16* lo = g_woutlo + (size_t)n * HID;
    for (int k4 = threadIdx.x; k4 < HID / 4; k4 += blockDim.x) {
        int k = k4 * 4;
        split4_store(*(const float4*)(row + k), &hi[k], &lo[k]);
    }
}

// ---------------- raw-mma split-bf16 GEMM: C[M,N] = A[M,K] @ W[N,K]^T ----------------
// C = Ahi*Whi + Ahi*Wlo + Alo*Whi  (fp32 accum, mma.sync m16n8k16).
// CTA 128M x 128N, 128 threads = 4 warps (2M x 2N), 64x64 per warp (unchanged body).
// 2-stage cp.async pipeline, 2 CTAs per SM -> independent barriers decorrelate
// the wait/sync dead windows that capped tensor% at 54 with one 8-warp CTA.
#define WLD    40                       // smem leading dim (elements); 80 B rows
#define A_EL   (128 * WLD)              // A matrix buffer elements (hi or lo)
#define W_EL   (128 * WLD)              // W matrix buffer elements (hi or lo)
#define STEL   (2 * A_EL + 2 * W_EL)    // per stage: [Ah][Al][Wh][Wl] = 20480 el

template <int PASS_ID>
__global__ __launch_bounds__(128, 2)
void gemm_mma_kernel()
{
    constexpr int N = (PASS_ID == 0) ? G4 : OUT_DIM;
    constexpr int K = (PASS_ID == 0) ? KX : HID;
    const __nv_bfloat16* __restrict__ Ahi = (PASS_ID == 0) ? g_xhi : g_hthi;
    const __nv_bfloat16* __restrict__ Alo = (PASS_ID == 0) ? g_xlo : g_htlo;
    const __nv_bfloat16* __restrict__ Whi = (PASS_ID == 0) ? g_whi : g_wouthi;
    const __nv_bfloat16* __restrict__ Wlo = (PASS_ID == 0) ? g_wlo : g_woutlo;
    float* __restrict__ C = (PASS_ID == 0) ? g_gates : g_logits;

    extern __shared__ __align__(16) __nv_bfloat16 smem[];   // 2 * STEL elements
    const uint32_t sbase = smem_u32(smem);

    const int tid  = threadIdx.x;
    const int lane = tid & 31;
    const int wid  = tid >> 5;
    const int warp_m = wid & 1;    // 2 warps over M, 64 rows each
    const int warp_n = wid >> 1;   // 2 warps over N, 64 cols each

    const int m0 = blockIdx.x * 128;
    const int n0 = blockIdx.y * 128;
    const int niter = K / 32;

    // ---- producer mapping: 16B chunks; A and W each 512/matrix -> 4 parts/thread
    const int rP = tid >> 2, cP = tid & 3;      // rP 0..31
    const __nv_bfloat16* pA[2][4];   // [hi/lo][part]
    const __nv_bfloat16* pW[2][4];
    uint32_t sOff[4];
#pragma unroll
    for (int p = 0; p < 4; p++) {
        const int r = rP + 32 * p;
        pA[0][p] = Ahi + (size_t)(m0 + r) * K + cP * 8;
        pA[1][p] = Alo + (size_t)(m0 + r) * K + cP * 8;
        pW[0][p] = Whi + (size_t)(n0 + r) * K + cP * 8;
        pW[1][p] = Wlo + (size_t)(n0 + r) * K + cP * 8;
        sOff[p]  = (uint32_t)(r * WLD + cP * 8) * 2;
    }

    auto issue_stage = [&](int stage, int it) {
        const uint32_t st = sbase + (uint32_t)(stage * STEL) * 2;
        const int k0 = it * 32;
#pragma unroll
        for (int p = 0; p < 4; p++) {
            cp16(st + sOff[p],                          pA[0][p] + k0);
            cp16(st + A_EL * 2 + sOff[p],               pA[1][p] + k0);
            cp16(st + 2 * A_EL * 2 + sOff[p],           pW[0][p] + k0);
            cp16(st + (2 * A_EL + W_EL) * 2 + sOff[p],  pW[1][p] + k0);
        }
    };

    // ---- consumer ldmatrix lane addressing (byte offsets within a matrix buffer)
    const uint32_t aLane = (uint32_t)(((warp_m * 64) + (lane & 7) + ((lane >> 3) & 1) * 8) * WLD
                                      + (lane >> 4) * 8) * 2;
    const uint32_t bLane = (uint32_t)(((warp_n * 64) + (lane & 7) + (lane >> 4) * 8) * WLD
                                      + ((lane >> 3) & 1) * 8) * 2;

    float acc[4][8][4];
#pragma unroll
    for (int mt = 0; mt < 4; mt++)
#pragma unroll
        for (int j = 0; j < 8; j++)
#pragma unroll
            for (int r = 0; r < 4; r++) acc[mt][j][r] = 0.f;

    // prologue: stage 0 in flight
    issue_stage(0, 0); cp_commit();

    int stage = 0;
    for (int it = 0; it < niter; ++it) {
        cp_wait0();        // stage it%2 loaded
        __syncthreads();   // all warps past iter it-1 compute (freed stage (it+1)%2)

        if (it + 1 < niter) issue_stage(stage ^ 1, it + 1);
        cp_commit();       // one group per iteration (may be empty at tail)

        const uint32_t sAh = sbase + (uint32_t)(stage * STEL) * 2;
        const uint32_t sAl = sAh + A_EL * 2;
        const uint32_t sWh = sAh + 2 * A_EL * 2;
        const uint32_t sWl = sAh + (2 * A_EL + W_EL) * 2;

#pragma unroll
        for (int kk = 0; kk < 2; ++kk) {
            const uint32_t kb = kk * 32;   // 16 elements = 32 bytes

            uint32_t ah[4][4], al[4][4], bhf[16], blf[16];
#pragma unroll
            for (int mt = 0; mt < 4; ++mt) {
                const uint32_t ra = (uint32_t)(mt * 16 * WLD) * 2 + aLane + kb;
                ldsm4(ah[mt], sAh + ra);
                ldsm4(al[mt], sAl + ra);
            }
#pragma unroll
            for (int np = 0; np < 4; ++np) {
                const uint32_t rb = (uint32_t)(np * 16 * WLD) * 2 + bLane + kb;
                ldsm4(&bhf[4 * np], sWh + rb);
                ldsm4(&blf[4 * np], sWl + rb);
            }
            // term-outermost: acc reuse distance 32 MMAs
#pragma unroll
            for (int mt = 0; mt < 4; ++mt)
#pragma unroll
                for (int j = 0; j < 8; ++j)
                    mma16816(acc[mt][j], ah[mt], bhf[2 * j], bhf[2 * j + 1]);
#pragma unroll
            for (int mt = 0; mt < 4; ++mt)
#pragma unroll
                for (int j = 0; j < 8; ++j)
                    mma16816(acc[mt][j], ah[mt], blf[2 * j], blf[2 * j + 1]);
#pragma unroll
            for (int mt = 0; mt < 4; ++mt)
#pragma unroll
                for (int j = 0; j < 8; ++j)
                    mma16816(acc[mt][j], al[mt], bhf[2 * j], bhf[2 * j + 1]);
        }
        stage ^= 1;
    }

    // ---- epilogue: m16n8 frag -> d0,d1 @(row,col), d2,d3 @(row+8,col)
    const int erow = lane >> 2;
    const int ecol = (lane & 3) * 2;
    float* Cw = C + (size_t)(m0 + warp_m * 64) * N + n0 + warp_n * 64;
#pragma unroll
    for (int mt = 0; mt < 4; ++mt)
#pragma unroll
        for (int j = 0; j < 8; ++j) {
            float* p0 = Cw + (size_t)(mt * 16 + erow) * N + j * 8 + ecol;
            *(float2*)p0                   = make_float2(acc[mt][j][0], acc[mt][j][1]);
            *(float2*)(p0 + (size_t)8 * N) = make_float2(acc[mt][j][2], acc[mt][j][3]);
        }
}

// ---------------- LSTM elementwise ----------------
__global__ void lstm_act_kernel(const float* __restrict__ cin,
                                const float* __restrict__ bf, const float* __restrict__ bi,
                                const float* __restrict__ bc, const float* __restrict__ bo,
                                float* __restrict__ out_it, float* __restrict__ out_ht,
                                float* __restrict__ out_ct)
{
    int idx = blockIdx.x * blockDim.x + threadIdx.x;
    if (idx >= BATCH * HID) return;
    int b = idx / HID;
    int j = idx - b * HID;
    const float* g = g_gates + (size_t)b * G4;
    float fp = g[j]           + bf[j];
    float ip = g[HID + j]     + bi[j];
    float cp = g[2 * HID + j] + bc[j];
    float op = g[3 * HID + j] + bo[j];
    float ft = 1.f / (1.f + __expf(-fp));
    float it = 1.f / (1.f + __expf(-ip));
    float cb = tanhf(cp);
    float ct = ft * cin[idx] + it * cb;
    float ot = 1.f / (1.f + __expf(-op));
    float ht = ot * tanhf(ct);
    out_it[idx] = it;
    out_ht[idx] = ht;
    out_ct[idx] = ct;
    __nv_bfloat16 hh = __float2bfloat16(ht);
    g_hthi[idx] = hh;
    g_htlo[idx] = __float2bfloat16(ht - __bfloat162float(hh));
}

// ---------------- log_softmax ----------------
__global__ void logsoftmax_kernel(const float* __restrict__ bout,
                                  float* __restrict__ out)
{
    const int row = blockIdx.x;
    const float* x = g_logits + (size_t)row * OUT_DIM;
    float* y = out + (size_t)row * OUT_DIM;
    __shared__ float red[256];
    const int tid = threadIdx.x;

    float mx = -INFINITY;
    for (int j = tid; j < OUT_DIM; j += 256) mx = fmaxf(mx, x[j] + bout[j]);
    red[tid] = mx; __syncthreads();
    for (int s = 128; s > 0; s >>= 1) {
        if (tid < s) red[tid] = fmaxf(red[tid], red[tid + s]);
        __syncthreads();
    }
    mx = red[0];
    __syncthreads();

    float sum = 0.f;
    for (int j = tid; j < OUT_DIM; j += 256) sum += __expf(x[j] + bout[j] - mx);
    red[tid] = sum; __syncthreads();
    for (int s = 128; s > 0; s >>= 1) {
        if (tid < s) red[tid] += red[tid + s];
        __syncthreads();
    }
    float lse = mx + logf(red[0]);

    for (int j = tid; j < OUT_DIM; j += 256) y[j] = x[j] + bout[j] - lse;
}

// ---------------- launch ----------------
extern "C" void kernel_launch(void* const* d_in, const int* in_sizes, int n_in,
                              void* d_out, int out_size)
{
    const float* in_i  = (const float*)d_in[0];
    const float* in_h  = (const float*)d_in[1];
    const float* in_c  = (const float*)d_in[2];
    const float* Wf    = (const float*)d_in[3];
    const float* bf_   = (const float*)d_in[4];
    const float* Wi    = (const float*)d_in[5];
    const float* bi_   = (const float*)d_in[6];
    const float* Wc    = (const float*)d_in[7];
    const float* bc_   = (const float*)d_in[8];
    const float* Wo    = (const float*)d_in[9];
    const float* bo_   = (const float*)d_in[10];
    const float* Wout  = (const float*)d_in[11];
    const float* bout  = (const float*)d_in[12];

    float* out    = (float*)d_out;
    float* out_it = out;
    float* out_ht = out + (size_t)BATCH * HID;
    float* out_ct = out + 2 * (size_t)BATCH * HID;
    float* out_ls = out + 3 * (size_t)BATCH * HID;

    const int SMEM_DYN = 2 * STEL * 2;   // 2 stages * 40960 B = 81920
    cudaFuncSetAttribute(gemm_mma_kernel<0>,
                         cudaFuncAttributeMaxDynamicSharedMemorySize, SMEM_DYN);
    cudaFuncSetAttribute(gemm_mma_kernel<1>,
                         cudaFuncAttributeMaxDynamicSharedMemorySize, SMEM_DYN);

    // 1) fp32 -> bf16 hi/lo conversions (vectorized)
    convert_x_kernel<<<BATCH, 256>>>(in_i, in_h);
    convert_w_kernel<<<G4, 256>>>(Wf, Wi, Wc, Wo);
    convert_wout_kernel<<<OUT_DIM, 256>>>(Wout);

    // 2) gates = x @ [Wf;Wi;Wc;Wo]^T
    {
        dim3 grid(BATCH / 128, G4 / 128);
        gemm_mma_kernel<0><<<grid, 128, SMEM_DYN>>>();
    }

    // 3) elementwise LSTM cell -> it, ht, ct (+ ht split)
    {
        int total = BATCH * HID;
        lstm_act_kernel<<<(total + 255) / 256, 256>>>(in_c, bf_, bi_, bc_, bo_,
                                                      out_it, out_ht, out_ct);
    }

    // 4) logits = ht @ Wout^T
    {
        dim3 grid(BATCH / 128, OUT_DIM / 128);
        gemm_mma_kernel<1><<<grid, 128, SMEM_DYN>>>();
    }

    // 5) log_softmax(logits + bout) -> out
    logsoftmax_kernel<<<BATCH, 256>>>(bout, out_ls);
}

// round 14
// speedup vs baseline: 6.9457x; 2.3885x over previous
#include <cuda_runtime.h>
#include <cuda_fp16.h>
#include <math.h>
#include <stdint.h>

// Problem dims (fixed per reference)
#define BATCH   1024
#define IN_DIM  1024
#define HID     4096
#define KX      (IN_DIM + HID)   // 5120
#define G4      (4 * HID)        // 16384
#define OUT_DIM 4096

// ---------------- scratch (no cudaMalloc allowed) ----------------
// Referenced ONLY inside device code (host-side use would get the host shadow).
__device__ __align__(16) __half g_xh[BATCH * KX];
__device__ __align__(16) __half g_wh[(size_t)G4 * KX];
__device__ __align__(16) __half g_wouth[(size_t)OUT_DIM * HID];
__device__ __align__(16) __half g_hth[BATCH * HID];
__device__ float g_gates[(size_t)BATCH * G4];
__device__ float g_logits[(size_t)BATCH * OUT_DIM];

// ---------------- PTX helpers ----------------
__device__ __forceinline__ uint32_t smem_u32(const void* p) {
    uint32_t a;
    asm("{ .reg .u64 t; cvta.to.shared.u64 t, %1; cvt.u32.u64 %0, t; }" : "=r"(a) : "l"(p));
    return a;
}
__device__ __forceinline__ void cp16(uint32_t s, const void* g) {
    asm volatile("cp.async.cg.shared.global [%0], [%1], 16;" :: "r"(s), "l"(g) : "memory");
}
__device__ __forceinline__ void cp_commit() {
    asm volatile("cp.async.commit_group;" ::: "memory");
}
__device__ __forceinline__ void cp_wait1() {
    asm volatile("cp.async.wait_group 1;" ::: "memory");
}
__device__ __forceinline__ void ldsm4(uint32_t* r, uint32_t addr) {
    asm volatile("ldmatrix.sync.aligned.m8n8.x4.shared.b16 {%0,%1,%2,%3}, [%4];"
                 : "=r"(r[0]), "=r"(r[1]), "=r"(r[2]), "=r"(r[3]) : "r"(addr));
}
__device__ __forceinline__ void mma16816(float* d, const uint32_t* a, uint32_t b0, uint32_t b1) {
    asm volatile("mma.sync.aligned.m16n8k16.row.col.f32.f16.f16.f32 "
                 "{%0,%1,%2,%3}, {%4,%5,%6,%7}, {%8,%9}, {%0,%1,%2,%3};"
                 : "+f"(d[0]), "+f"(d[1]), "+f"(d[2]), "+f"(d[3])
                 : "r"(a[0]), "r"(a[1]), "r"(a[2]), "r"(a[3]), "r"(b0), "r"(b1));
}

// ---------------- fp32 -> fp16 converters (vectorized) ----------------
__device__ __forceinline__ void cvt4_store(float4 v, __half* dst) {
    __half2 h0 = __floats2half2_rn(v.x, v.y);
    __half2 h1 = __floats2half2_rn(v.z, v.w);
    uint2 u;
    u.x = *(uint32_t*)&h0;
    u.y = *(uint32_t*)&h1;
    *(uint2*)dst = u;
}

__global__ void convert_x_kernel(const float* __restrict__ i_, const float* __restrict__ h_) {
    const int b = blockIdx.x;
    for (int k4 = threadIdx.x; k4 < KX / 4; k4 += blockDim.x) {
        int k = k4 * 4;
        float4 v = (k < IN_DIM) ? *(const float4*)(i_ + (size_t)b * IN_DIM + k)
                                : *(const float4*)(h_ + (size_t)b * HID + (k - IN_DIM));
        cvt4_store(v, &g_xh[(size_t)b * KX + k]);
    }
}

__global__ void convert_w_kernel(const float* __restrict__ Wf, const float* __restrict__ Wi,
                                 const float* __restrict__ Wc, const float* __restrict__ Wo) {
    const int n = blockIdx.x;                 // stacked weight row (0..16383)
    const int gate = n >> 12;
    const int nl = n & (HID - 1);
    const float* src = (gate == 0) ? Wf : (gate == 1) ? Wi : (gate == 2) ? Wc : Wo;
    const float* row = src + (size_t)nl * KX;
    __half* dst = g_wh + (size_t)n * KX;
    for (int k4 = threadIdx.x; k4 < KX / 4; k4 += blockDim.x) {
        int k = k4 * 4;
        cvt4_store(*(const float4*)(row + k), &dst[k]);
    }
}

__global__ void convert_wout_kernel(const float* __restrict__ W) {
    const int n = blockIdx.x;
    const float* row = W + (size_t)n * HID;
    __half* dst = g_wouth + (size_t)n * HID;
    for (int k4 = threadIdx.x; k4 < HID / 4; k4 += blockDim.x) {
        int k = k4 * 4;
        cvt4_store(*(const float4*)(row + k), &dst[k]);
    }
}

// ---------------- single-pass fp16 GEMM: C[M,N] = A[M,K] @ W[N,K]^T ----------------
// fp32 accum via mma.sync m16n8k16.f16. CTA 128M x 128N, 4 warps (2Mx2N, 64x64 each),
// k-step 64, 3-stage cp.async pipeline (distance 2), 2 CTAs/SM (decorrelated stalls).
#define WLD   72                        // smem leading dim (elements); 144 B rows
#define A_EL  (128 * WLD)               // one matrix buffer (A or W)
#define STEL  (2 * A_EL)                // per stage: [A][W] = 18432 el = 36864 B

template <int PASS_ID>
__global__ __launch_bounds__(128, 2)
void gemm_mma_kernel()
{
    constexpr int N = (PASS_ID == 0) ? G4 : OUT_DIM;
    constexpr int K = (PASS_ID == 0) ? KX : HID;
    const __half* __restrict__ A = (PASS_ID == 0) ? g_xh : g_hth;
    const __half* __restrict__ W = (PASS_ID == 0) ? g_wh : g_wouth;
    float* __restrict__ C = (PASS_ID == 0) ? g_gates : g_logits;

    extern __shared__ __align__(16) __half smem[];   // 3 * STEL elements
    const uint32_t sbase = smem_u32(smem);

    const int tid  = threadIdx.x;
    const int lane = tid & 31;
    const int wid  = tid >> 5;
    const int warp_m = wid & 1;    // 2 warps over M, 64 rows each
    const int warp_n = wid >> 1;   // 2 warps over N, 64 cols each

    const int m0 = blockIdx.x * 128;
    const int n0 = blockIdx.y * 128;
    const int niter = K / 64;

    // ---- producer mapping: row has 8x16B chunks; thread -> row rP(+16p), chunk cP
    const int rP = tid >> 3, cP = tid & 7;   // rP 0..15
    const __half* baseA = A + (size_t)(m0 + rP) * K + cP * 8;
    const __half* baseW = W + (size_t)(n0 + rP) * K + cP * 8;
    const uint32_t sOffBase = (uint32_t)(rP * WLD + cP * 8) * 2;

    auto issue_stage = [&](int stage, int it) {
        const uint32_t st = sbase + (uint32_t)(stage * STEL) * 2;
        const int k0 = it * 64;
#pragma unroll
        for (int p = 0; p < 8; p++) {
            const uint32_t so = sOffBase + (uint32_t)(p * 16 * WLD) * 2;
            cp16(st + so,              baseA + (size_t)(p * 16) * K + k0);
            cp16(st + A_EL * 2 + so,   baseW + (size_t)(p * 16) * K + k0);
        }
    };

    // ---- consumer ldmatrix lane addressing (byte offsets within a matrix buffer)
    const uint32_t aLane = (uint32_t)(((warp_m * 64) + (lane & 7) + ((lane >> 3) & 1) * 8) * WLD
                                      + (lane >> 4) * 8) * 2;
    const uint32_t bLane = (uint32_t)(((warp_n * 64) + (lane & 7) + (lane >> 4) * 8) * WLD
                                      + ((lane >> 3) & 1) * 8) * 2;

    float acc[4][8][4];
#pragma unroll
    for (int mt = 0; mt < 4; mt++)
#pragma unroll
        for (int j = 0; j < 8; j++)
#pragma unroll
            for (int r = 0; r < 4; r++) acc[mt][j][r] = 0.f;

    // prologue: stages 0 and 1 in flight
    issue_stage(0, 0); cp_commit();
    issue_stage(1, 1); cp_commit();

    int stage = 0;
    for (int it = 0; it < niter; ++it) {
        cp_wait1();        // group for `it` done (group it+1 may be pending)
        __syncthreads();   // all warps past iter it-1; stage (it+2)%3 has no readers

        if (it + 2 < niter) issue_stage((stage + 2) % 3, it + 2);
        cp_commit();       // one group per iteration (may be empty at tail)

        const uint32_t sA = sbase + (uint32_t)(stage * STEL) * 2;
        const uint32_t sW = sA + A_EL * 2;

#pragma unroll
        for (int kk = 0; kk < 4; ++kk) {
            const uint32_t kb = kk * 32;   // 16 elements = 32 bytes

            uint32_t af[4][4], bf[16];
#pragma unroll
            for (int mt = 0; mt < 4; ++mt)
                ldsm4(af[mt], sA + (uint32_t)(mt * 16 * WLD) * 2 + aLane + kb);
#pragma unroll
            for (int np = 0; np < 4; ++np)
                ldsm4(&bf[4 * np], sW + (uint32_t)(np * 16 * WLD) * 2 + bLane + kb);

#pragma unroll
            for (int mt = 0; mt < 4; ++mt)
#pragma unroll
                for (int j = 0; j < 8; ++j)
                    mma16816(acc[mt][j], af[mt], bf[2 * j], bf[2 * j + 1]);
        }
        stage = (stage + 1) % 3;
    }

    // ---- epilogue: m16n8 frag -> d0,d1 @(row,col), d2,d3 @(row+8,col)
    const int erow = lane >> 2;
    const int ecol = (lane & 3) * 2;
    float* Cw = C + (size_t)(m0 + warp_m * 64) * N + n0 + warp_n * 64;
#pragma unroll
    for (int mt = 0; mt < 4; ++mt)
#pragma unroll
        for (int j = 0; j < 8; ++j) {
            float* p0 = Cw + (size_t)(mt * 16 + erow) * N + j * 8 + ecol;
            *(float2*)p0                   = make_float2(acc[mt][j][0], acc[mt][j][1]);
            *(float2*)(p0 + (size_t)8 * N) = make_float2(acc[mt][j][2], acc[mt][j][3]);
        }
}

// ---------------- LSTM elementwise ----------------
__global__ void lstm_act_kernel(const float* __restrict__ cin,
                                const float* __restrict__ bf, const float* __restrict__ bi,
                                const float* __restrict__ bc, const float* __restrict__ bo,
                                float* __restrict__ out_it, float* __restrict__ out_ht,
                                float* __restrict__ out_ct)
{
    int idx = blockIdx.x * blockDim.x + threadIdx.x;
    if (idx >= BATCH * HID) return;
    int b = idx / HID;
    int j = idx - b * HID;
    const float* g = g_gates + (size_t)b * G4;
    float fp = g[j]           + bf[j];
    float ip = g[HID + j]     + bi[j];
    float cp = g[2 * HID + j] + bc[j];
    float op = g[3 * HID + j] + bo[j];
    float ft = 1.f / (1.f + __expf(-fp));
    float it = 1.f / (1.f + __expf(-ip));
    float cb = tanhf(cp);
    float ct = ft * cin[idx] + it * cb;
    float ot = 1.f / (1.f + __expf(-op));
    float ht = ot * tanhf(ct);
    out_it[idx] = it;
    out_ht[idx] = ht;
    out_ct[idx] = ct;
    g_hth[idx] = __float2half(ht);
}

// ---------------- log_softmax ----------------
__global__ void logsoftmax_kernel(const float* __restrict__ bout,
                                  float* __restrict__ out)
{
    const int row = blockIdx.x;
    const float* x = g_logits + (size_t)row * OUT_DIM;
    float* y = out + (size_t)row * OUT_DIM;
    __shared__ float red[256];
    const int tid = threadIdx.x;

    float mx = -INFINITY;
    for (int j = tid; j < OUT_DIM; j += 256) mx = fmaxf(mx, x[j] + bout[j]);
    red[tid] = mx; __syncthreads();
    for (int s = 128; s > 0; s >>= 1) {
        if (tid < s) red[tid] = fmaxf(red[tid], red[tid + s]);
        __syncthreads();
    }
    mx = red[0];
    __syncthreads();

    float sum = 0.f;
    for (int j = tid; j < OUT_DIM; j += 256) sum += __expf(x[j] + bout[j] - mx);
    red[tid] = sum; __syncthreads();
    for (int s = 128; s > 0; s >>= 1) {
        if (tid < s) red[tid] += red[tid + s];
        __syncthreads();
    }
    float lse = mx + logf(red[0]);

    for (int j = tid; j < OUT_DIM; j += 256) y[j] = x[j] + bout[j] - lse;
}

// ---------------- launch ----------------
extern "C" void kernel_launch(void* const* d_in, const int* in_sizes, int n_in,
                              void* d_out, int out_size)
{
    const float* in_i  = (const float*)d_in[0];
    const float* in_h  = (const float*)d_in[1];
    const float* in_c  = (const float*)d_in[2];
    const float* Wf    = (const float*)d_in[3];
    const float* bf_   = (const float*)d_in[4];
    const float* Wi    = (const float*)d_in[5];
    const float* bi_   = (const float*)d_in[6];
    const float* Wc    = (const float*)d_in[7];
    const float* bc_   = (const float*)d_in[8];
    const float* Wo    = (const float*)d_in[9];
    const float* bo_   = (const float*)d_in[10];
    const float* Wout  = (const float*)d_in[11];
    const float* bout  = (const float*)d_in[12];

    float* out    = (float*)d_out;
    float* out_it = out;
    float* out_ht = out + (size_t)BATCH * HID;
    float* out_ct = out + 2 * (size_t)BATCH * HID;
    float* out_ls = out + 3 * (size_t)BATCH * HID;

    const int SMEM_DYN = 3 * STEL * 2;   // 3 stages * 36864 B = 110592
    cudaFuncSetAttribute(gemm_mma_kernel<0>,
                         cudaFuncAttributeMaxDynamicSharedMemorySize, SMEM_DYN);
    cudaFuncSetAttribute(gemm_mma_kernel<1>,
                         cudaFuncAttributeMaxDynamicSharedMemorySize, SMEM_DYN);

    // 1) fp32 -> fp16 conversions (vectorized)
    convert_x_kernel<<<BATCH, 256>>>(in_i, in_h);
    convert_w_kernel<<<G4, 256>>>(Wf, Wi, Wc, Wo);
    convert_wout_kernel<<<OUT_DIM, 256>>>(Wout);

    // 2) gates = x @ [Wf;Wi;Wc;Wo]^T  (single-pass fp16, fp32 accum)
    {
        dim3 grid(BATCH / 128, G4 / 128);
        gemm_mma_kernel<0><<<grid, 128, SMEM_DYN>>>();
    }

    // 3) elementwise LSTM cell -> it, ht, ct (+ ht fp16)
    {
        int total = BATCH * HID;
        lstm_act_kernel<<<(total + 255) / 256, 256>>>(in_c, bf_, bi_, bc_, bo_,
                                                      out_it, out_ht, out_ct);
    }

    // 4) logits = ht @ Wout^T
    {
        dim3 grid(BATCH / 128, OUT_DIM / 128);
        gemm_mma_kernel<1><<<grid, 128, SMEM_DYN>>>();
    }

    // 5) log_softmax(logits + bout) -> out
    logsoftmax_kernel<<<BATCH, 256>>>(bout, out_ls);
}